// round 1
// baseline (speedup 1.0000x reference)
#include <cuda_runtime.h>
#include <cuda_bf16.h>

// Problem constants
#define S_LEN 4096
#define D_MODEL 2048
#define NH 16
#define NG 4
#define HD 128
#define KV_D (NG * HD)          // 512
#define SOFTMAX_SCALE 0.08838834764831845f  // 1/sqrt(128)

// Scratch (no cudaMalloc allowed)
__device__ float g_q[S_LEN * D_MODEL];   // 32 MB
__device__ float g_k[S_LEN * KV_D];      // 8 MB
__device__ float g_v[S_LEN * KV_D];      // 8 MB
__device__ float g_ctx[S_LEN * D_MODEL]; // 32 MB

// ---------------------------------------------------------------------------
// SGEMM: C[M,N] = A[M,K] @ B[K,N], all row-major fp32.
// 128x128 block tile, BK=8, 256 threads, 8x8 register microtile.
// M,N,K all multiples of 128/8 here -> no bounds checks.
// ---------------------------------------------------------------------------
__global__ __launch_bounds__(256) void sgemm128(const float* __restrict__ A,
                                                const float* __restrict__ B,
                                                float* __restrict__ C,
                                                int M, int N, int K) {
    __shared__ float As[8][128];   // transposed A tile: As[k][m]
    __shared__ float Bs[8][128];   // Bs[k][n]

    const int bx = blockIdx.x;     // N tile
    const int by = blockIdx.y;     // M tile
    const int tid = threadIdx.x;

    // A tile load mapping: 128 rows x 8 cols, one float4 per thread
    const int arow = tid >> 1;           // 0..127
    const int acol = (tid & 1) << 2;     // 0 or 4
    // B tile load mapping: 8 rows x 128 cols, one float4 per thread
    const int brow = tid >> 5;           // 0..7
    const int bcol = (tid & 31) << 2;    // 0..124

    const float* Aptr = A + (size_t)(by * 128 + arow) * K + acol;
    const float* Bptr = B + (size_t)brow * N + bx * 128 + bcol;

    const int ty = tid >> 4;             // 0..15
    const int tx = tid & 15;             // 0..15
    const int rowBase = ty * 8;
    const int colBase = tx * 8;

    float acc[8][8];
#pragma unroll
    for (int i = 0; i < 8; i++)
#pragma unroll
        for (int j = 0; j < 8; j++) acc[i][j] = 0.0f;

    for (int k0 = 0; k0 < K; k0 += 8) {
        float4 a4 = *(const float4*)Aptr;
        float4 b4 = *(const float4*)Bptr;
        As[acol + 0][arow] = a4.x;
        As[acol + 1][arow] = a4.y;
        As[acol + 2][arow] = a4.z;
        As[acol + 3][arow] = a4.w;
        *(float4*)&Bs[brow][bcol] = b4;
        __syncthreads();

#pragma unroll
        for (int kk = 0; kk < 8; kk++) {
            float4 a0 = *(float4*)&As[kk][rowBase];
            float4 a1 = *(float4*)&As[kk][rowBase + 4];
            float4 b0 = *(float4*)&Bs[kk][colBase];
            float4 b1 = *(float4*)&Bs[kk][colBase + 4];
            float ar[8] = {a0.x, a0.y, a0.z, a0.w, a1.x, a1.y, a1.z, a1.w};
            float br[8] = {b0.x, b0.y, b0.z, b0.w, b1.x, b1.y, b1.z, b1.w};
#pragma unroll
            for (int i = 0; i < 8; i++)
#pragma unroll
                for (int j = 0; j < 8; j++)
                    acc[i][j] = fmaf(ar[i], br[j], acc[i][j]);
        }
        __syncthreads();
        Aptr += 8;
        Bptr += (size_t)8 * N;
    }

    float* Cptr = C + (size_t)(by * 128 + rowBase) * N + bx * 128 + colBase;
#pragma unroll
    for (int i = 0; i < 8; i++) {
        float4 c0 = make_float4(acc[i][0], acc[i][1], acc[i][2], acc[i][3]);
        float4 c1 = make_float4(acc[i][4], acc[i][5], acc[i][6], acc[i][7]);
        *(float4*)(Cptr + (size_t)i * N) = c0;
        *(float4*)(Cptr + (size_t)i * N + 4) = c1;
    }
}

// ---------------------------------------------------------------------------
// RoPE, in place. t: [S, nh*128]. One thread per (s, h, d<64) pair.
// out[d]    = t[d]*cos[s,d]    - t[d+64]*sin[s,d]
// out[d+64] = t[d+64]*cos[s,d+64] + t[d]*sin[s,d+64]
// ---------------------------------------------------------------------------
__global__ void rope_kernel(float* __restrict__ t,
                            const float* __restrict__ cosp,
                            const float* __restrict__ sinp,
                            int nh, int total) {
    int idx = blockIdx.x * blockDim.x + threadIdx.x;
    if (idx >= total) return;
    int d = idx & 63;
    int h = (idx >> 6) % nh;
    int s = idx / (64 * nh);
    float* row = t + (size_t)s * (nh * 128) + h * 128;
    float c1 = cosp[s * 128 + d];
    float s1 = sinp[s * 128 + d];
    float c2 = cosp[s * 128 + d + 64];
    float s2 = sinp[s * 128 + d + 64];
    float a = row[d];
    float b = row[d + 64];
    row[d]      = a * c1 - b * s1;
    row[d + 64] = b * c2 + a * s2;
}

// ---------------------------------------------------------------------------
// Flash attention, fp32, causal. One block = (64-query tile, head).
// smem: Qs/Ks/Vs [64][132], Ps [64][68]  (~116 KB dynamic).
// 256 threads: thread (ty,tx) with ty=tid/16, tx=tid%16 owns
// score subtile rows ty*4..+3, cols tx*4..+3, and O cols tx*8..+7.
// ---------------------------------------------------------------------------
#define FA_LDQ 132
#define FA_LDP 68
#define FA_SMEM ((3 * 64 * FA_LDQ + 64 * FA_LDP) * 4)

__global__ __launch_bounds__(256) void flash_attn(const float* __restrict__ Q,
                                                  const float* __restrict__ K,
                                                  const float* __restrict__ V,
                                                  float* __restrict__ O) {
    extern __shared__ float sm[];
    float* Qs = sm;                      // 64 x 132
    float* Ks = sm + 64 * FA_LDQ;        // 64 x 132
    float* Vs = sm + 2 * 64 * FA_LDQ;    // 64 x 132
    float* Ps = sm + 3 * 64 * FA_LDQ;    // 64 x 68

    const int qt = blockIdx.x;
    const int h = blockIdx.y;
    const int g = h >> 2;                // GS = 4
    const int tid = threadIdx.x;
    const int tx = tid & 15;
    const int ty = tid >> 4;
    const int q0 = qt * 64;

    // Load Q tile (64 x 128)
    for (int t = tid; t < 64 * 32; t += 256) {
        int r = t >> 5;
        int c4 = (t & 31) << 2;
        *(float4*)&Qs[r * FA_LDQ + c4] =
            *(const float4*)(Q + (size_t)(q0 + r) * D_MODEL + h * HD + c4);
    }

    float m_i[4], l_i[4], acc[4][8];
#pragma unroll
    for (int i = 0; i < 4; i++) {
        m_i[i] = -1e30f;
        l_i[i] = 0.0f;
#pragma unroll
        for (int d = 0; d < 8; d++) acc[i][d] = 0.0f;
    }

    for (int jt = 0; jt <= qt; ++jt) {
        __syncthreads();  // previous Ps/Vs consumers done; Qs visible on first iter
        for (int t = tid; t < 64 * 32; t += 256) {
            int r = t >> 5;
            int c4 = (t & 31) << 2;
            size_t goff = (size_t)(jt * 64 + r) * KV_D + g * HD + c4;
            *(float4*)&Ks[r * FA_LDQ + c4] = *(const float4*)(K + goff);
            *(float4*)&Vs[r * FA_LDQ + c4] = *(const float4*)(V + goff);
        }
        __syncthreads();

        // S = Q K^T (64x64), each thread 4x4
        float s[4][4];
#pragma unroll
        for (int i = 0; i < 4; i++)
#pragma unroll
            for (int j = 0; j < 4; j++) s[i][j] = 0.0f;

        for (int d0 = 0; d0 < HD; d0 += 4) {
            float4 q4[4], k4[4];
#pragma unroll
            for (int i = 0; i < 4; i++)
                q4[i] = *(float4*)&Qs[(ty * 4 + i) * FA_LDQ + d0];
#pragma unroll
            for (int j = 0; j < 4; j++)
                k4[j] = *(float4*)&Ks[(tx * 4 + j) * FA_LDQ + d0];
#pragma unroll
            for (int i = 0; i < 4; i++)
#pragma unroll
                for (int j = 0; j < 4; j++) {
                    s[i][j] = fmaf(q4[i].x, k4[j].x, s[i][j]);
                    s[i][j] = fmaf(q4[i].y, k4[j].y, s[i][j]);
                    s[i][j] = fmaf(q4[i].z, k4[j].z, s[i][j]);
                    s[i][j] = fmaf(q4[i].w, k4[j].w, s[i][j]);
                }
        }

        // scale + causal mask + row max (per-thread part)
        const bool diag = (jt == qt);
        float cur_m[4];
#pragma unroll
        for (int i = 0; i < 4; i++) {
            float mm = -1e30f;
            int gi = q0 + ty * 4 + i;
#pragma unroll
            for (int j = 0; j < 4; j++) {
                float sv = s[i][j] * SOFTMAX_SCALE;
                int gj = jt * 64 + tx * 4 + j;
                if (diag && gj > gi) sv = -1e30f;
                s[i][j] = sv;
                mm = fmaxf(mm, sv);
            }
            cur_m[i] = mm;
        }
        // reduce max across the 16 tx lanes (same half-warp)
#pragma unroll
        for (int off = 8; off; off >>= 1)
#pragma unroll
            for (int i = 0; i < 4; i++)
                cur_m[i] = fmaxf(cur_m[i],
                                 __shfl_xor_sync(0xffffffffu, cur_m[i], off));

        float alpha[4], rowsum[4];
#pragma unroll
        for (int i = 0; i < 4; i++) {
            float mn = fmaxf(m_i[i], cur_m[i]);
            alpha[i] = __expf(m_i[i] - mn);
            m_i[i] = mn;
            float rs = 0.0f;
#pragma unroll
            for (int j = 0; j < 4; j++) {
                float p = __expf(s[i][j] - mn);
                Ps[(ty * 4 + i) * FA_LDP + tx * 4 + j] = p;
                rs += p;
            }
            rowsum[i] = rs;
        }
#pragma unroll
        for (int off = 8; off; off >>= 1)
#pragma unroll
            for (int i = 0; i < 4; i++)
                rowsum[i] += __shfl_xor_sync(0xffffffffu, rowsum[i], off);
#pragma unroll
        for (int i = 0; i < 4; i++) {
            l_i[i] = l_i[i] * alpha[i] + rowsum[i];
#pragma unroll
            for (int d = 0; d < 8; d++) acc[i][d] *= alpha[i];
        }
        __syncthreads();  // Ps visible to all

        // O += P @ V ; thread owns cols tx*8..+7
        for (int j = 0; j < 64; ++j) {
            float4 v0 = *(float4*)&Vs[j * FA_LDQ + tx * 8];
            float4 v1 = *(float4*)&Vs[j * FA_LDQ + tx * 8 + 4];
#pragma unroll
            for (int i = 0; i < 4; i++) {
                float p = Ps[(ty * 4 + i) * FA_LDP + j];
                acc[i][0] = fmaf(p, v0.x, acc[i][0]);
                acc[i][1] = fmaf(p, v0.y, acc[i][1]);
                acc[i][2] = fmaf(p, v0.z, acc[i][2]);
                acc[i][3] = fmaf(p, v0.w, acc[i][3]);
                acc[i][4] = fmaf(p, v1.x, acc[i][4]);
                acc[i][5] = fmaf(p, v1.y, acc[i][5]);
                acc[i][6] = fmaf(p, v1.z, acc[i][6]);
                acc[i][7] = fmaf(p, v1.w, acc[i][7]);
            }
        }
    }

    // epilogue: normalize and write ctx[s, h*128 + d]
#pragma unroll
    for (int i = 0; i < 4; i++) {
        float inv = 1.0f / l_i[i];
        int row = q0 + ty * 4 + i;
        float4 o0 = make_float4(acc[i][0] * inv, acc[i][1] * inv,
                                acc[i][2] * inv, acc[i][3] * inv);
        float4 o1 = make_float4(acc[i][4] * inv, acc[i][5] * inv,
                                acc[i][6] * inv, acc[i][7] * inv);
        float* dst = O + (size_t)row * D_MODEL + h * HD + tx * 8;
        *(float4*)dst = o0;
        *(float4*)(dst + 4) = o1;
    }
}

// ---------------------------------------------------------------------------
extern "C" void kernel_launch(void* const* d_in, const int* in_sizes, int n_in,
                              void* d_out, int out_size) {
    const float* x    = (const float*)d_in[0];
    // d_in[1] = mask (causal, recomputed analytically -> unused)
    const float* wq   = (const float*)d_in[2];
    const float* wk   = (const float*)d_in[3];
    const float* wv   = (const float*)d_in[4];
    const float* wo   = (const float*)d_in[5];
    const float* cosp = (const float*)d_in[6];
    const float* sinp = (const float*)d_in[7];
    float* out = (float*)d_out;

    float *q, *k, *v, *ctx;
    cudaGetSymbolAddress((void**)&q, g_q);
    cudaGetSymbolAddress((void**)&k, g_k);
    cudaGetSymbolAddress((void**)&v, g_v);
    cudaGetSymbolAddress((void**)&ctx, g_ctx);

    // Projections
    sgemm128<<<dim3(D_MODEL / 128, S_LEN / 128), 256>>>(x, wq, q, S_LEN, D_MODEL, D_MODEL);
    sgemm128<<<dim3(KV_D / 128, S_LEN / 128), 256>>>(x, wk, k, S_LEN, KV_D, D_MODEL);
    sgemm128<<<dim3(KV_D / 128, S_LEN / 128), 256>>>(x, wv, v, S_LEN, KV_D, D_MODEL);

    // RoPE on q and k
    {
        int totq = S_LEN * NH * 64;
        rope_kernel<<<(totq + 255) / 256, 256>>>(q, cosp, sinp, NH, totq);
        int totk = S_LEN * NG * 64;
        rope_kernel<<<(totk + 255) / 256, 256>>>(k, cosp, sinp, NG, totk);
    }

    // Flash attention
    cudaFuncSetAttribute(flash_attn, cudaFuncAttributeMaxDynamicSharedMemorySize,
                         FA_SMEM);
    flash_attn<<<dim3(S_LEN / 64, NH), 256, FA_SMEM>>>(q, k, v, ctx);

    // Output projection
    sgemm128<<<dim3(D_MODEL / 128, S_LEN / 128), 256>>>(ctx, wo, out, S_LEN, D_MODEL, D_MODEL);
}

// round 4
// speedup vs baseline: 1.3088x; 1.3088x over previous
#include <cuda_runtime.h>
#include <cuda_bf16.h>
#include <cstdint>

// Problem constants
#define S_LEN 4096
#define D_MODEL 2048
#define NH 16
#define NG 4
#define HD 128
#define KV_D (NG * HD)          // 512
#define SOFTMAX_SCALE 0.08838834764831845f  // 1/sqrt(128)

// Scratch (no cudaMalloc allowed)
__device__ float g_q[S_LEN * D_MODEL];   // 32 MB
__device__ float g_k[S_LEN * KV_D];      // 8 MB
__device__ float g_v[S_LEN * KV_D];      // 8 MB
__device__ float g_ctx[S_LEN * D_MODEL]; // 32 MB
__device__ float g_wqT[D_MODEL * D_MODEL]; // [N=2048, K=2048]
__device__ float g_wkT[KV_D * D_MODEL];    // [N=512,  K=2048]
__device__ float g_wvT[KV_D * D_MODEL];
__device__ float g_woT[D_MODEL * D_MODEL];

// ---------------------------------------------------------------------------
// Helpers
// ---------------------------------------------------------------------------
__device__ __forceinline__ uint32_t smem_to_u32(const void* p) {
    uint32_t a;
    asm("{ .reg .u64 t; cvta.to.shared.u64 t, %1; cvt.u32.u64 %0, t; }"
        : "=r"(a) : "l"(p));
    return a;
}

__device__ __forceinline__ void cp_async16(uint32_t smem_addr, const void* gptr) {
    asm volatile("cp.async.cg.shared.global [%0], [%1], 16;" :: "r"(smem_addr), "l"(gptr));
}
__device__ __forceinline__ void cp_async_commit() {
    asm volatile("cp.async.commit_group;" ::: "memory");
}
template <int N>
__device__ __forceinline__ void cp_async_wait() {
    asm volatile("cp.async.wait_group %0;" :: "n"(N) : "memory");
}

// pack two fp32 -> bf16x2 (x -> low half, y -> high half)
__device__ __forceinline__ uint32_t pack_bf16(float x, float y) {
    uint32_t r;
    asm("cvt.rn.bf16x2.f32 %0, %1, %2;" : "=r"(r) : "f"(y), "f"(x));
    return r;
}
__device__ __forceinline__ float bf16lo_f32(uint32_t h) { return __uint_as_float(h << 16); }
__device__ __forceinline__ float bf16hi_f32(uint32_t h) { return __uint_as_float(h & 0xffff0000u); }

// split float2 into (hi, lo) bf16x2 pair: f = hi + lo (to ~19 bits)
__device__ __forceinline__ void split_bf16(float2 f, uint32_t& hi, uint32_t& lo) {
    hi = pack_bf16(f.x, f.y);
    float rx = f.x - bf16lo_f32(hi);
    float ry = f.y - bf16hi_f32(hi);
    lo = pack_bf16(rx, ry);
}

// mma.sync m16n8k16 bf16 row.col, fp32 accumulate
__device__ __forceinline__ void mma_bf16(float* c, const uint32_t* a, const uint32_t* b) {
    asm volatile(
        "mma.sync.aligned.m16n8k16.row.col.f32.bf16.bf16.f32 "
        "{%0,%1,%2,%3}, {%4,%5,%6,%7}, {%8,%9}, {%0,%1,%2,%3};"
        : "+f"(c[0]), "+f"(c[1]), "+f"(c[2]), "+f"(c[3])
        : "r"(a[0]), "r"(a[1]), "r"(a[2]), "r"(a[3]), "r"(b[0]), "r"(b[1]));
}

// ---------------------------------------------------------------------------
// GEMM (bf16x3 compensated): C[M,N] = A[M,K] @ Bt[N,K]^T, fp32 in/out.
// 128x128 CTA tile, BK=32, 8 warps (2x4), warp tile 64x32.
// Double-buffered cp.async staging of fp32 tiles; hi/lo bf16 split in regs.
// ---------------------------------------------------------------------------
#define BK 32
#define SROW 40                         // padded row stride in words
#define STAGE_WORDS (128 * SROW)        // per matrix per stage
#define GM_SMEM (2 * 2 * STAGE_WORDS * 4)  // A,B x 2 stages = 81920 B

__global__ __launch_bounds__(256) void gemm_bf16x3(const float* __restrict__ A,
                                                   const float* __restrict__ Bt,
                                                   float* __restrict__ C,
                                                   int M, int N, int K) {
    extern __shared__ char sm[];
    float* smf = (float*)sm;
    float* As = smf;                       // [2][128][SROW]
    float* Bs = smf + 2 * STAGE_WORDS;     // [2][128][SROW]
    const uint32_t smem_u32 = smem_to_u32(sm);

    const int tid = threadIdx.x;
    const int wid = tid >> 5;
    const int lane = tid & 31;
    const int g = lane >> 2;       // group id 0..7
    const int tig = lane & 3;      // thread in group 0..3
    const int wm = wid >> 2;       // 0..1
    const int wn = wid & 3;        // 0..3
    const int m0 = blockIdx.y * 128;
    const int n0 = blockIdx.x * 128;
    const int NS = K / BK;

    // cp.async chunk mapping: 1024 chunks per matrix per stage (128 rows x 8)
    // thread handles 4 A-chunks + 4 B-chunks
    auto load_stage = [&](int s, int buf) {
        const int k0 = s * BK;
#pragma unroll
        for (int i = 0; i < 4; i++) {
            int c = tid + i * 256;        // 0..1023
            int row = c >> 3;
            int cc = c & 7;
            uint32_t dstA = smem_u32 + (buf * STAGE_WORDS + row * SROW + cc * 4) * 4;
            uint32_t dstB = dstA + 2 * STAGE_WORDS * 4;
            cp_async16(dstA, A + (size_t)(m0 + row) * K + k0 + cc * 4);
            cp_async16(dstB, Bt + (size_t)(n0 + row) * K + k0 + cc * 4);
        }
    };

    float acc[4][4][4];
#pragma unroll
    for (int m = 0; m < 4; m++)
#pragma unroll
        for (int n = 0; n < 4; n++)
#pragma unroll
            for (int i = 0; i < 4; i++) acc[m][n][i] = 0.0f;

    load_stage(0, 0);
    cp_async_commit();
    load_stage(1, 1);
    cp_async_commit();

    for (int s = 0; s < NS; s++) {
        const int buf = s & 1;
        cp_async_wait<1>();
        __syncthreads();

        const float* as = As + buf * STAGE_WORDS;
        const float* bs = Bs + buf * STAGE_WORDS;

#pragma unroll
        for (int ks = 0; ks < BK; ks += 16) {
            // B fragments: 4 n-tiles
            uint32_t bhi[4][2], blo[4][2];
#pragma unroll
            for (int n = 0; n < 4; n++) {
                const float* brow = bs + (wn * 32 + n * 8 + g) * SROW + ks + tig * 2;
                float2 f0 = *(const float2*)(brow);
                float2 f1 = *(const float2*)(brow + 8);
                split_bf16(f0, bhi[n][0], blo[n][0]);
                split_bf16(f1, bhi[n][1], blo[n][1]);
            }
#pragma unroll
            for (int m = 0; m < 4; m++) {
                const float* ar0 = as + (wm * 64 + m * 16 + g) * SROW + ks + tig * 2;
                const float* ar1 = ar0 + 8 * SROW;
                float2 f00 = *(const float2*)(ar0);
                float2 f10 = *(const float2*)(ar1);
                float2 f01 = *(const float2*)(ar0 + 8);
                float2 f11 = *(const float2*)(ar1 + 8);
                uint32_t ahi[4], alo[4];
                split_bf16(f00, ahi[0], alo[0]);
                split_bf16(f10, ahi[1], alo[1]);
                split_bf16(f01, ahi[2], alo[2]);
                split_bf16(f11, ahi[3], alo[3]);
#pragma unroll
                for (int n = 0; n < 4; n++) {
                    mma_bf16(acc[m][n], ahi, bhi[n]);
                    mma_bf16(acc[m][n], ahi, blo[n]);
                    mma_bf16(acc[m][n], alo, bhi[n]);
                }
            }
        }

        __syncthreads();
        if (s + 2 < NS) load_stage(s + 2, buf);
        cp_async_commit();
    }

    // Epilogue
#pragma unroll
    for (int m = 0; m < 4; m++) {
        int r0 = m0 + wm * 64 + m * 16 + g;
        int r1 = r0 + 8;
#pragma unroll
        for (int n = 0; n < 4; n++) {
            int col = n0 + wn * 32 + n * 8 + tig * 2;
            *(float2*)(C + (size_t)r0 * N + col) = make_float2(acc[m][n][0], acc[m][n][1]);
            *(float2*)(C + (size_t)r1 * N + col) = make_float2(acc[m][n][2], acc[m][n][3]);
        }
    }
}

// ---------------------------------------------------------------------------
// Transpose: out[N,K] = in[K,N]. Dims multiples of 32.
// ---------------------------------------------------------------------------
__global__ void transpose_kernel(const float* __restrict__ in,
                                 float* __restrict__ out, int R, int Ccols) {
    __shared__ float t[32][33];
    int c0 = blockIdx.x * 32, r0 = blockIdx.y * 32;
    int x = threadIdx.x, y = threadIdx.y;  // 32 x 8
#pragma unroll
    for (int i = y; i < 32; i += 8) t[i][x] = in[(size_t)(r0 + i) * Ccols + c0 + x];
    __syncthreads();
#pragma unroll
    for (int i = y; i < 32; i += 8) out[(size_t)(c0 + i) * R + r0 + x] = t[x][i];
}

// ---------------------------------------------------------------------------
// RoPE, in place. t: [S, nh*128].
// ---------------------------------------------------------------------------
__global__ void rope_kernel(float* __restrict__ t,
                            const float* __restrict__ cosp,
                            const float* __restrict__ sinp,
                            int nh, int total) {
    int idx = blockIdx.x * blockDim.x + threadIdx.x;
    if (idx >= total) return;
    int d = idx & 63;
    int h = (idx >> 6) % nh;
    int s = idx / (64 * nh);
    float* row = t + (size_t)s * (nh * 128) + h * 128;
    float c1 = cosp[s * 128 + d];
    float s1 = sinp[s * 128 + d];
    float c2 = cosp[s * 128 + d + 64];
    float s2 = sinp[s * 128 + d + 64];
    float a = row[d];
    float b = row[d + 64];
    row[d]      = a * c1 - b * s1;
    row[d + 64] = b * c2 + a * s2;
}

// ---------------------------------------------------------------------------
// Flash attention, fp32, causal (unchanged; round-5 target).
// ---------------------------------------------------------------------------
#define FA_LDQ 132
#define FA_LDP 68
#define FA_SMEM ((3 * 64 * FA_LDQ + 64 * FA_LDP) * 4)

__global__ __launch_bounds__(256) void flash_attn(const float* __restrict__ Q,
                                                  const float* __restrict__ K,
                                                  const float* __restrict__ V,
                                                  float* __restrict__ O) {
    extern __shared__ char sm[];
    float* smf = (float*)sm;
    float* Qs = smf;
    float* Ks = smf + 64 * FA_LDQ;
    float* Vs = smf + 2 * 64 * FA_LDQ;
    float* Ps = smf + 3 * 64 * FA_LDQ;

    const int qt = blockIdx.x;
    const int h = blockIdx.y;
    const int g = h >> 2;
    const int tid = threadIdx.x;
    const int tx = tid & 15;
    const int ty = tid >> 4;
    const int q0 = qt * 64;

    for (int t = tid; t < 64 * 32; t += 256) {
        int r = t >> 5;
        int c4 = (t & 31) << 2;
        *(float4*)&Qs[r * FA_LDQ + c4] =
            *(const float4*)(Q + (size_t)(q0 + r) * D_MODEL + h * HD + c4);
    }

    float m_i[4], l_i[4], acc[4][8];
#pragma unroll
    for (int i = 0; i < 4; i++) {
        m_i[i] = -1e30f;
        l_i[i] = 0.0f;
#pragma unroll
        for (int d = 0; d < 8; d++) acc[i][d] = 0.0f;
    }

    for (int jt = 0; jt <= qt; ++jt) {
        __syncthreads();
        for (int t = tid; t < 64 * 32; t += 256) {
            int r = t >> 5;
            int c4 = (t & 31) << 2;
            size_t goff = (size_t)(jt * 64 + r) * KV_D + g * HD + c4;
            *(float4*)&Ks[r * FA_LDQ + c4] = *(const float4*)(K + goff);
            *(float4*)&Vs[r * FA_LDQ + c4] = *(const float4*)(V + goff);
        }
        __syncthreads();

        float s[4][4];
#pragma unroll
        for (int i = 0; i < 4; i++)
#pragma unroll
            for (int j = 0; j < 4; j++) s[i][j] = 0.0f;

        for (int d0 = 0; d0 < HD; d0 += 4) {
            float4 q4[4], k4[4];
#pragma unroll
            for (int i = 0; i < 4; i++)
                q4[i] = *(float4*)&Qs[(ty * 4 + i) * FA_LDQ + d0];
#pragma unroll
            for (int j = 0; j < 4; j++)
                k4[j] = *(float4*)&Ks[(tx * 4 + j) * FA_LDQ + d0];
#pragma unroll
            for (int i = 0; i < 4; i++)
#pragma unroll
                for (int j = 0; j < 4; j++) {
                    s[i][j] = fmaf(q4[i].x, k4[j].x, s[i][j]);
                    s[i][j] = fmaf(q4[i].y, k4[j].y, s[i][j]);
                    s[i][j] = fmaf(q4[i].z, k4[j].z, s[i][j]);
                    s[i][j] = fmaf(q4[i].w, k4[j].w, s[i][j]);
                }
        }

        const bool diag = (jt == qt);
        float cur_m[4];
#pragma unroll
        for (int i = 0; i < 4; i++) {
            float mm = -1e30f;
            int gi = q0 + ty * 4 + i;
#pragma unroll
            for (int j = 0; j < 4; j++) {
                float sv = s[i][j] * SOFTMAX_SCALE;
                int gj = jt * 64 + tx * 4 + j;
                if (diag && gj > gi) sv = -1e30f;
                s[i][j] = sv;
                mm = fmaxf(mm, sv);
            }
            cur_m[i] = mm;
        }
#pragma unroll
        for (int off = 8; off; off >>= 1)
#pragma unroll
            for (int i = 0; i < 4; i++)
                cur_m[i] = fmaxf(cur_m[i],
                                 __shfl_xor_sync(0xffffffffu, cur_m[i], off));

        float alpha[4], rowsum[4];
#pragma unroll
        for (int i = 0; i < 4; i++) {
            float mn = fmaxf(m_i[i], cur_m[i]);
            alpha[i] = __expf(m_i[i] - mn);
            m_i[i] = mn;
            float rs = 0.0f;
#pragma unroll
            for (int j = 0; j < 4; j++) {
                float p = __expf(s[i][j] - mn);
                Ps[(ty * 4 + i) * FA_LDP + tx * 4 + j] = p;
                rs += p;
            }
            rowsum[i] = rs;
        }
#pragma unroll
        for (int off = 8; off; off >>= 1)
#pragma unroll
            for (int i = 0; i < 4; i++)
                rowsum[i] += __shfl_xor_sync(0xffffffffu, rowsum[i], off);
#pragma unroll
        for (int i = 0; i < 4; i++) {
            l_i[i] = l_i[i] * alpha[i] + rowsum[i];
#pragma unroll
            for (int d = 0; d < 8; d++) acc[i][d] *= alpha[i];
        }
        __syncthreads();

        for (int j = 0; j < 64; ++j) {
            float4 v0 = *(float4*)&Vs[j * FA_LDQ + tx * 8];
            float4 v1 = *(float4*)&Vs[j * FA_LDQ + tx * 8 + 4];
#pragma unroll
            for (int i = 0; i < 4; i++) {
                float p = Ps[(ty * 4 + i) * FA_LDP + j];
                acc[i][0] = fmaf(p, v0.x, acc[i][0]);
                acc[i][1] = fmaf(p, v0.y, acc[i][1]);
                acc[i][2] = fmaf(p, v0.z, acc[i][2]);
                acc[i][3] = fmaf(p, v0.w, acc[i][3]);
                acc[i][4] = fmaf(p, v1.x, acc[i][4]);
                acc[i][5] = fmaf(p, v1.y, acc[i][5]);
                acc[i][6] = fmaf(p, v1.z, acc[i][6]);
                acc[i][7] = fmaf(p, v1.w, acc[i][7]);
            }
        }
    }

#pragma unroll
    for (int i = 0; i < 4; i++) {
        float inv = 1.0f / l_i[i];
        int row = q0 + ty * 4 + i;
        float4 o0 = make_float4(acc[i][0] * inv, acc[i][1] * inv,
                                acc[i][2] * inv, acc[i][3] * inv);
        float4 o1 = make_float4(acc[i][4] * inv, acc[i][5] * inv,
                                acc[i][6] * inv, acc[i][7] * inv);
        float* dst = O + (size_t)row * D_MODEL + h * HD + tx * 8;
        *(float4*)dst = o0;
        *(float4*)(dst + 4) = o1;
    }
}

// ---------------------------------------------------------------------------
extern "C" void kernel_launch(void* const* d_in, const int* in_sizes, int n_in,
                              void* d_out, int out_size) {
    const float* x    = (const float*)d_in[0];
    // d_in[1] = mask (causal, recomputed analytically -> unused)
    const float* wq   = (const float*)d_in[2];
    const float* wk   = (const float*)d_in[3];
    const float* wv   = (const float*)d_in[4];
    const float* wo   = (const float*)d_in[5];
    const float* cosp = (const float*)d_in[6];
    const float* sinp = (const float*)d_in[7];
    float* out = (float*)d_out;

    float *q, *k, *v, *ctx, *wqT, *wkT, *wvT, *woT;
    cudaGetSymbolAddress((void**)&q, g_q);
    cudaGetSymbolAddress((void**)&k, g_k);
    cudaGetSymbolAddress((void**)&v, g_v);
    cudaGetSymbolAddress((void**)&ctx, g_ctx);
    cudaGetSymbolAddress((void**)&wqT, g_wqT);
    cudaGetSymbolAddress((void**)&wkT, g_wkT);
    cudaGetSymbolAddress((void**)&wvT, g_wvT);
    cudaGetSymbolAddress((void**)&woT, g_woT);

    cudaFuncSetAttribute(gemm_bf16x3, cudaFuncAttributeMaxDynamicSharedMemorySize, GM_SMEM);
    cudaFuncSetAttribute(flash_attn, cudaFuncAttributeMaxDynamicSharedMemorySize, FA_SMEM);

    // Transpose weights to [N, K] K-major
    transpose_kernel<<<dim3(D_MODEL / 32, D_MODEL / 32), dim3(32, 8)>>>(wq, wqT, D_MODEL, D_MODEL);
    transpose_kernel<<<dim3(KV_D / 32, D_MODEL / 32), dim3(32, 8)>>>(wk, wkT, D_MODEL, KV_D);
    transpose_kernel<<<dim3(KV_D / 32, D_MODEL / 32), dim3(32, 8)>>>(wv, wvT, D_MODEL, KV_D);
    transpose_kernel<<<dim3(D_MODEL / 32, D_MODEL / 32), dim3(32, 8)>>>(wo, woT, D_MODEL, D_MODEL);

    // Projections on tensor cores (bf16x3 compensated mma.sync)
    gemm_bf16x3<<<dim3(D_MODEL / 128, S_LEN / 128), 256, GM_SMEM>>>(x, wqT, q, S_LEN, D_MODEL, D_MODEL);
    gemm_bf16x3<<<dim3(KV_D / 128, S_LEN / 128), 256, GM_SMEM>>>(x, wkT, k, S_LEN, KV_D, D_MODEL);
    gemm_bf16x3<<<dim3(KV_D / 128, S_LEN / 128), 256, GM_SMEM>>>(x, wvT, v, S_LEN, KV_D, D_MODEL);

    // RoPE on q and k
    {
        int totq = S_LEN * NH * 64;
        rope_kernel<<<(totq + 255) / 256, 256>>>(q, cosp, sinp, NH, totq);
        int totk = S_LEN * NG * 64;
        rope_kernel<<<(totk + 255) / 256, 256>>>(k, cosp, sinp, NG, totk);
    }

    // Flash attention (fp32 FFMA — next round's target)
    flash_attn<<<dim3(S_LEN / 64, NH), 256, FA_SMEM>>>(q, k, v, ctx);

    // Output projection
    gemm_bf16x3<<<dim3(D_MODEL / 128, S_LEN / 128), 256, GM_SMEM>>>(ctx, woT, out, S_LEN, D_MODEL, D_MODEL);
}

// round 5
// speedup vs baseline: 3.3294x; 2.5439x over previous
#include <cuda_runtime.h>
#include <cuda_bf16.h>
#include <cstdint>

// Problem constants
#define S_LEN 4096
#define D_MODEL 2048
#define NH 16
#define NG 4
#define HD 128
#define KV_D (NG * HD)          // 512
#define SOFTMAX_SCALE 0.08838834764831845f  // 1/sqrt(128)

// Scratch (no cudaMalloc allowed)
__device__ float g_q[S_LEN * D_MODEL];
__device__ float g_k[S_LEN * KV_D];
__device__ float g_v[S_LEN * KV_D];
__device__ float g_ctx[S_LEN * D_MODEL];
__device__ float g_wqT[D_MODEL * D_MODEL];
__device__ float g_wkT[KV_D * D_MODEL];
__device__ float g_wvT[KV_D * D_MODEL];
__device__ float g_woT[D_MODEL * D_MODEL];

// ---------------------------------------------------------------------------
// Helpers
// ---------------------------------------------------------------------------
__device__ __forceinline__ uint32_t smem_to_u32(const void* p) {
    uint32_t a;
    asm("{ .reg .u64 t; cvta.to.shared.u64 t, %1; cvt.u32.u64 %0, t; }"
        : "=r"(a) : "l"(p));
    return a;
}

__device__ __forceinline__ void cp_async16(uint32_t smem_addr, const void* gptr) {
    asm volatile("cp.async.cg.shared.global [%0], [%1], 16;" :: "r"(smem_addr), "l"(gptr));
}
__device__ __forceinline__ void cp_async_commit() {
    asm volatile("cp.async.commit_group;" ::: "memory");
}
template <int N>
__device__ __forceinline__ void cp_async_wait() {
    asm volatile("cp.async.wait_group %0;" :: "n"(N) : "memory");
}

// pack two fp32 -> bf16x2 (x -> low half, y -> high half)
__device__ __forceinline__ uint32_t pack_bf16(float x, float y) {
    uint32_t r;
    asm("cvt.rn.bf16x2.f32 %0, %1, %2;" : "=r"(r) : "f"(y), "f"(x));
    return r;
}
__device__ __forceinline__ float bf16lo_f32(uint32_t h) { return __uint_as_float(h << 16); }
__device__ __forceinline__ float bf16hi_f32(uint32_t h) { return __uint_as_float(h & 0xffff0000u); }

// split float2 into (hi, lo) bf16x2 pair: f = hi + lo (to ~19 bits)
__device__ __forceinline__ void split_bf16(float2 f, uint32_t& hi, uint32_t& lo) {
    hi = pack_bf16(f.x, f.y);
    float rx = f.x - bf16lo_f32(hi);
    float ry = f.y - bf16hi_f32(hi);
    lo = pack_bf16(rx, ry);
}

// mma.sync m16n8k16 bf16 row.col, fp32 accumulate
__device__ __forceinline__ void mma_bf16(float* c, const uint32_t* a, const uint32_t* b) {
    asm volatile(
        "mma.sync.aligned.m16n8k16.row.col.f32.bf16.bf16.f32 "
        "{%0,%1,%2,%3}, {%4,%5,%6,%7}, {%8,%9}, {%0,%1,%2,%3};"
        : "+f"(c[0]), "+f"(c[1]), "+f"(c[2]), "+f"(c[3])
        : "r"(a[0]), "r"(a[1]), "r"(a[2]), "r"(a[3]), "r"(b[0]), "r"(b[1]));
}

__device__ __forceinline__ void ldsm_x4(uint32_t* r, uint32_t addr) {
    asm volatile("ldmatrix.sync.aligned.m8n8.x4.shared.b16 {%0,%1,%2,%3}, [%4];"
        : "=r"(r[0]), "=r"(r[1]), "=r"(r[2]), "=r"(r[3]) : "r"(addr));
}
__device__ __forceinline__ void ldsm_x2(uint32_t* r, uint32_t addr) {
    asm volatile("ldmatrix.sync.aligned.m8n8.x2.shared.b16 {%0,%1}, [%2];"
        : "=r"(r[0]), "=r"(r[1]) : "r"(addr));
}

// ---------------------------------------------------------------------------
// GEMM (bf16x3 compensated): C[M,N] = A[M,K] @ Bt[N,K]^T, fp32 in/out.
// ---------------------------------------------------------------------------
#define BK 32
#define SROW 40
#define STAGE_WORDS (128 * SROW)
#define GM_SMEM (2 * 2 * STAGE_WORDS * 4)

__global__ __launch_bounds__(256) void gemm_bf16x3(const float* __restrict__ A,
                                                   const float* __restrict__ Bt,
                                                   float* __restrict__ C,
                                                   int M, int N, int K) {
    extern __shared__ char sm[];
    float* smf = (float*)sm;
    float* As = smf;
    float* Bs = smf + 2 * STAGE_WORDS;
    const uint32_t smem_u32 = smem_to_u32(sm);

    const int tid = threadIdx.x;
    const int wid = tid >> 5;
    const int lane = tid & 31;
    const int g = lane >> 2;
    const int tig = lane & 3;
    const int wm = wid >> 2;
    const int wn = wid & 3;
    const int m0 = blockIdx.y * 128;
    const int n0 = blockIdx.x * 128;
    const int NS = K / BK;

    auto load_stage = [&](int s, int buf) {
        const int k0 = s * BK;
#pragma unroll
        for (int i = 0; i < 4; i++) {
            int c = tid + i * 256;
            int row = c >> 3;
            int cc = c & 7;
            uint32_t dstA = smem_u32 + (buf * STAGE_WORDS + row * SROW + cc * 4) * 4;
            uint32_t dstB = dstA + 2 * STAGE_WORDS * 4;
            cp_async16(dstA, A + (size_t)(m0 + row) * K + k0 + cc * 4);
            cp_async16(dstB, Bt + (size_t)(n0 + row) * K + k0 + cc * 4);
        }
    };

    float acc[4][4][4];
#pragma unroll
    for (int m = 0; m < 4; m++)
#pragma unroll
        for (int n = 0; n < 4; n++)
#pragma unroll
            for (int i = 0; i < 4; i++) acc[m][n][i] = 0.0f;

    load_stage(0, 0);
    cp_async_commit();
    load_stage(1, 1);
    cp_async_commit();

    for (int s = 0; s < NS; s++) {
        const int buf = s & 1;
        cp_async_wait<1>();
        __syncthreads();

        const float* as = As + buf * STAGE_WORDS;
        const float* bs = Bs + buf * STAGE_WORDS;

#pragma unroll
        for (int ks = 0; ks < BK; ks += 16) {
            uint32_t bhi[4][2], blo[4][2];
#pragma unroll
            for (int n = 0; n < 4; n++) {
                const float* brow = bs + (wn * 32 + n * 8 + g) * SROW + ks + tig * 2;
                float2 f0 = *(const float2*)(brow);
                float2 f1 = *(const float2*)(brow + 8);
                split_bf16(f0, bhi[n][0], blo[n][0]);
                split_bf16(f1, bhi[n][1], blo[n][1]);
            }
#pragma unroll
            for (int m = 0; m < 4; m++) {
                const float* ar0 = as + (wm * 64 + m * 16 + g) * SROW + ks + tig * 2;
                const float* ar1 = ar0 + 8 * SROW;
                float2 f00 = *(const float2*)(ar0);
                float2 f10 = *(const float2*)(ar1);
                float2 f01 = *(const float2*)(ar0 + 8);
                float2 f11 = *(const float2*)(ar1 + 8);
                uint32_t ahi[4], alo[4];
                split_bf16(f00, ahi[0], alo[0]);
                split_bf16(f10, ahi[1], alo[1]);
                split_bf16(f01, ahi[2], alo[2]);
                split_bf16(f11, ahi[3], alo[3]);
#pragma unroll
                for (int n = 0; n < 4; n++) {
                    mma_bf16(acc[m][n], ahi, bhi[n]);
                    mma_bf16(acc[m][n], ahi, blo[n]);
                    mma_bf16(acc[m][n], alo, bhi[n]);
                }
            }
        }

        __syncthreads();
        if (s + 2 < NS) load_stage(s + 2, buf);
        cp_async_commit();
    }

#pragma unroll
    for (int m = 0; m < 4; m++) {
        int r0 = m0 + wm * 64 + m * 16 + g;
        int r1 = r0 + 8;
#pragma unroll
        for (int n = 0; n < 4; n++) {
            int col = n0 + wn * 32 + n * 8 + tig * 2;
            *(float2*)(C + (size_t)r0 * N + col) = make_float2(acc[m][n][0], acc[m][n][1]);
            *(float2*)(C + (size_t)r1 * N + col) = make_float2(acc[m][n][2], acc[m][n][3]);
        }
    }
}

// ---------------------------------------------------------------------------
// Transpose: out[N,K] = in[K,N].
// ---------------------------------------------------------------------------
__global__ void transpose_kernel(const float* __restrict__ in,
                                 float* __restrict__ out, int R, int Ccols) {
    __shared__ float t[32][33];
    int c0 = blockIdx.x * 32, r0 = blockIdx.y * 32;
    int x = threadIdx.x, y = threadIdx.y;
#pragma unroll
    for (int i = y; i < 32; i += 8) t[i][x] = in[(size_t)(r0 + i) * Ccols + c0 + x];
    __syncthreads();
#pragma unroll
    for (int i = y; i < 32; i += 8) out[(size_t)(c0 + i) * R + r0 + x] = t[x][i];
}

// ---------------------------------------------------------------------------
// RoPE, in place.
// ---------------------------------------------------------------------------
__global__ void rope_kernel(float* __restrict__ t,
                            const float* __restrict__ cosp,
                            const float* __restrict__ sinp,
                            int nh, int total) {
    int idx = blockIdx.x * blockDim.x + threadIdx.x;
    if (idx >= total) return;
    int d = idx & 63;
    int h = (idx >> 6) % nh;
    int s = idx / (64 * nh);
    float* row = t + (size_t)s * (nh * 128) + h * 128;
    float c1 = cosp[s * 128 + d];
    float s1 = sinp[s * 128 + d];
    float c2 = cosp[s * 128 + d + 64];
    float s2 = sinp[s * 128 + d + 64];
    float a = row[d];
    float b = row[d + 64];
    row[d]      = a * c1 - b * s1;
    row[d + 64] = b * c2 + a * s2;
}

// ---------------------------------------------------------------------------
// Flash attention on mma.sync (bf16x3 compensated), causal.
// CTA: 128 q-rows x 1 head, 8 warps (16 rows each), KV tiles of 64 tokens.
// Q,K hi/lo bf16 in smem (row stride 136 -> ldmatrix conflict-free),
// V stored transposed VT[d][token] (stride 72).
// ---------------------------------------------------------------------------
#define QLD 136
#define VLD 72
#define OFF_QHI 0
#define OFF_QLO 34816
#define OFF_KHI 69632
#define OFF_KLO 87040
#define OFF_VTHI 104448
#define OFF_VTLO 122880
#define FB_SMEM 141312

__global__ __launch_bounds__(256, 1) void flash_attn_mma(const float* __restrict__ Q,
                                                         const float* __restrict__ K,
                                                         const float* __restrict__ V,
                                                         float* __restrict__ O) {
    extern __shared__ char sm[];
    const uint32_t smem_u32 = smem_to_u32(sm);

    const int qt = blockIdx.x;
    const int h = blockIdx.y;
    const int kvg = h >> 2;
    const int tid = threadIdx.x;
    const int w = tid >> 5;
    const int lane = tid & 31;
    const int lg = lane >> 2;
    const int tig = lane & 3;
    const int q0 = qt * 128;
    const int qb = w * 16;

    // --- Load Q tile (scale folded), split hi/lo into smem ---
    for (int c = tid; c < 128 * 32; c += 256) {
        int row = c >> 5;
        int col4 = (c & 31) << 2;
        float4 v = *(const float4*)(Q + (size_t)(q0 + row) * D_MODEL + h * HD + col4);
        v.x *= SOFTMAX_SCALE; v.y *= SOFTMAX_SCALE; v.z *= SOFTMAX_SCALE; v.w *= SOFTMAX_SCALE;
        uint32_t h01, l01, h23, l23;
        split_bf16(make_float2(v.x, v.y), h01, l01);
        split_bf16(make_float2(v.z, v.w), h23, l23);
        uint32_t off = (row * QLD + col4) * 2;
        *(uint32_t*)(sm + OFF_QHI + off) = h01;
        *(uint32_t*)(sm + OFF_QHI + off + 4) = h23;
        *(uint32_t*)(sm + OFF_QLO + off) = l01;
        *(uint32_t*)(sm + OFF_QLO + off + 4) = l23;
    }

    // ldmatrix per-thread address invariants
    const int lr = lane & 7;
    const int lb8 = (lane >> 3) & 1;
    const int lb16 = (lane >> 4) & 1;
    const uint32_t qa_hi = smem_u32 + OFF_QHI + ((qb + lr + lb8 * 8) * QLD + lb16 * 8) * 2;
    const uint32_t qa_lo = qa_hi + (OFF_QLO - OFF_QHI);
    const uint32_t kb_hi = smem_u32 + OFF_KHI + (lr * QLD + lb8 * 8) * 2;
    const uint32_t kb_lo = kb_hi + (OFF_KLO - OFF_KHI);
    const uint32_t vb_hi = smem_u32 + OFF_VTHI + (lr * VLD + lb8 * 8) * 2;
    const uint32_t vb_lo = vb_hi + (OFF_VTLO - OFF_VTHI);

    float m0 = -1e30f, m1 = -1e30f, l0 = 0.0f, l1 = 0.0f;
    float oacc[16][4];
#pragma unroll
    for (int nt = 0; nt < 16; nt++)
#pragma unroll
        for (int j = 0; j < 4; j++) oacc[nt][j] = 0.0f;

    const int njt = 2 * qt + 2;
    for (int jt = 0; jt < njt; jt++) {
        __syncthreads();
        // K tile: 64 x 128, split hi/lo
        for (int c = tid; c < 2048; c += 256) {
            int row = c >> 5;
            int col4 = (c & 31) << 2;
            float4 v = *(const float4*)(K + (size_t)(jt * 64 + row) * KV_D + kvg * HD + col4);
            uint32_t h01, l01, h23, l23;
            split_bf16(make_float2(v.x, v.y), h01, l01);
            split_bf16(make_float2(v.z, v.w), h23, l23);
            uint32_t off = (row * QLD + col4) * 2;
            *(uint32_t*)(sm + OFF_KHI + off) = h01;
            *(uint32_t*)(sm + OFF_KHI + off + 4) = h23;
            *(uint32_t*)(sm + OFF_KLO + off) = l01;
            *(uint32_t*)(sm + OFF_KLO + off + 4) = l23;
        }
        // V tile transposed: VT[d][token]
        for (int c = tid; c < 2048; c += 256) {
            int row = c & 63;           // token
            int col = (c >> 6) << 2;    // d base
            float4 v = *(const float4*)(V + (size_t)(jt * 64 + row) * KV_D + kvg * HD + col);
            float vv[4] = {v.x, v.y, v.z, v.w};
#pragma unroll
            for (int j = 0; j < 4; j++) {
                __nv_bfloat16 hb = __float2bfloat16(vv[j]);
                float r = vv[j] - __bfloat162float(hb);
                __nv_bfloat16 lb = __float2bfloat16(r);
                uint32_t off = ((col + j) * VLD + row) * 2;
                *(__nv_bfloat16*)(sm + OFF_VTHI + off) = hb;
                *(__nv_bfloat16*)(sm + OFF_VTLO + off) = lb;
            }
        }
        __syncthreads();

        // skip fully-masked warp tiles (diagonal upper part)
        if (jt * 64 > q0 + qb + 15) continue;

        // --- S = Q K^T (warp: 16 x 64), bf16x3 compensated ---
        float sacc[8][4];
#pragma unroll
        for (int nt = 0; nt < 8; nt++)
#pragma unroll
            for (int j = 0; j < 4; j++) sacc[nt][j] = 0.0f;

#pragma unroll
        for (int kc = 0; kc < 8; kc++) {
            uint32_t qhi[4], qlo[4];
            ldsm_x4(qhi, qa_hi + kc * 32);
            ldsm_x4(qlo, qa_lo + kc * 32);
#pragma unroll
            for (int nt = 0; nt < 8; nt++) {
                uint32_t khi[2], klo[2];
                uint32_t kaddr = kb_hi + nt * (8 * QLD * 2) + kc * 32;
                ldsm_x2(khi, kaddr);
                ldsm_x2(klo, kaddr + (OFF_KLO - OFF_KHI));
                mma_bf16(sacc[nt], qhi, khi);
                mma_bf16(sacc[nt], qhi, klo);
                mma_bf16(sacc[nt], qlo, khi);
            }
        }

        // --- mask + online softmax ---
        if (jt * 64 + 63 > q0 + qb) {
#pragma unroll
            for (int nt = 0; nt < 8; nt++)
#pragma unroll
                for (int j = 0; j < 4; j++) {
                    int gj = jt * 64 + nt * 8 + tig * 2 + (j & 1);
                    int gi = q0 + qb + lg + ((j >> 1) << 3);
                    if (gj > gi) sacc[nt][j] = -1e30f;
                }
        }

        float cur0 = -1e30f, cur1 = -1e30f;
#pragma unroll
        for (int nt = 0; nt < 8; nt++) {
            cur0 = fmaxf(cur0, fmaxf(sacc[nt][0], sacc[nt][1]));
            cur1 = fmaxf(cur1, fmaxf(sacc[nt][2], sacc[nt][3]));
        }
        cur0 = fmaxf(cur0, __shfl_xor_sync(0xffffffffu, cur0, 1));
        cur0 = fmaxf(cur0, __shfl_xor_sync(0xffffffffu, cur0, 2));
        cur1 = fmaxf(cur1, __shfl_xor_sync(0xffffffffu, cur1, 1));
        cur1 = fmaxf(cur1, __shfl_xor_sync(0xffffffffu, cur1, 2));

        float mn0 = fmaxf(m0, cur0), mn1 = fmaxf(m1, cur1);
        float alpha0 = __expf(m0 - mn0), alpha1 = __expf(m1 - mn1);
        m0 = mn0; m1 = mn1;

        float rs0 = 0.0f, rs1 = 0.0f;
#pragma unroll
        for (int nt = 0; nt < 8; nt++) {
            sacc[nt][0] = __expf(sacc[nt][0] - mn0);
            sacc[nt][1] = __expf(sacc[nt][1] - mn0);
            sacc[nt][2] = __expf(sacc[nt][2] - mn1);
            sacc[nt][3] = __expf(sacc[nt][3] - mn1);
            rs0 += sacc[nt][0] + sacc[nt][1];
            rs1 += sacc[nt][2] + sacc[nt][3];
        }
        rs0 += __shfl_xor_sync(0xffffffffu, rs0, 1);
        rs0 += __shfl_xor_sync(0xffffffffu, rs0, 2);
        rs1 += __shfl_xor_sync(0xffffffffu, rs1, 1);
        rs1 += __shfl_xor_sync(0xffffffffu, rs1, 2);
        l0 = l0 * alpha0 + rs0;
        l1 = l1 * alpha1 + rs1;

#pragma unroll
        for (int nt = 0; nt < 16; nt++) {
            oacc[nt][0] *= alpha0;
            oacc[nt][1] *= alpha0;
            oacc[nt][2] *= alpha1;
            oacc[nt][3] *= alpha1;
        }

        // --- O += P V (P from regs, V^T frags via ldmatrix) ---
#pragma unroll
        for (int kc = 0; kc < 4; kc++) {
            uint32_t ahi[4], alo[4];
            split_bf16(make_float2(sacc[2 * kc][0], sacc[2 * kc][1]), ahi[0], alo[0]);
            split_bf16(make_float2(sacc[2 * kc][2], sacc[2 * kc][3]), ahi[1], alo[1]);
            split_bf16(make_float2(sacc[2 * kc + 1][0], sacc[2 * kc + 1][1]), ahi[2], alo[2]);
            split_bf16(make_float2(sacc[2 * kc + 1][2], sacc[2 * kc + 1][3]), ahi[3], alo[3]);
#pragma unroll
            for (int nt = 0; nt < 16; nt++) {
                uint32_t vhi[2], vlo[2];
                uint32_t vaddr = vb_hi + nt * (8 * VLD * 2) + kc * 32;
                ldsm_x2(vhi, vaddr);
                ldsm_x2(vlo, vaddr + (OFF_VTLO - OFF_VTHI));
                mma_bf16(oacc[nt], ahi, vhi);
                mma_bf16(oacc[nt], alo, vhi);
                mma_bf16(oacc[nt], ahi, vlo);
            }
        }
    }

    // --- epilogue ---
    float inv0 = 1.0f / l0;
    float inv1 = 1.0f / l1;
    int row0 = q0 + qb + lg;
    int row1 = row0 + 8;
#pragma unroll
    for (int nt = 0; nt < 16; nt++) {
        int col = h * HD + nt * 8 + tig * 2;
        *(float2*)(O + (size_t)row0 * D_MODEL + col) =
            make_float2(oacc[nt][0] * inv0, oacc[nt][1] * inv0);
        *(float2*)(O + (size_t)row1 * D_MODEL + col) =
            make_float2(oacc[nt][2] * inv1, oacc[nt][3] * inv1);
    }
}

// ---------------------------------------------------------------------------
extern "C" void kernel_launch(void* const* d_in, const int* in_sizes, int n_in,
                              void* d_out, int out_size) {
    const float* x    = (const float*)d_in[0];
    const float* wq   = (const float*)d_in[2];
    const float* wk   = (const float*)d_in[3];
    const float* wv   = (const float*)d_in[4];
    const float* wo   = (const float*)d_in[5];
    const float* cosp = (const float*)d_in[6];
    const float* sinp = (const float*)d_in[7];
    float* out = (float*)d_out;

    float *q, *k, *v, *ctx, *wqT, *wkT, *wvT, *woT;
    cudaGetSymbolAddress((void**)&q, g_q);
    cudaGetSymbolAddress((void**)&k, g_k);
    cudaGetSymbolAddress((void**)&v, g_v);
    cudaGetSymbolAddress((void**)&ctx, g_ctx);
    cudaGetSymbolAddress((void**)&wqT, g_wqT);
    cudaGetSymbolAddress((void**)&wkT, g_wkT);
    cudaGetSymbolAddress((void**)&wvT, g_wvT);
    cudaGetSymbolAddress((void**)&woT, g_woT);

    cudaFuncSetAttribute(gemm_bf16x3, cudaFuncAttributeMaxDynamicSharedMemorySize, GM_SMEM);
    cudaFuncSetAttribute(flash_attn_mma, cudaFuncAttributeMaxDynamicSharedMemorySize, FB_SMEM);

    transpose_kernel<<<dim3(D_MODEL / 32, D_MODEL / 32), dim3(32, 8)>>>(wq, wqT, D_MODEL, D_MODEL);
    transpose_kernel<<<dim3(KV_D / 32, D_MODEL / 32), dim3(32, 8)>>>(wk, wkT, D_MODEL, KV_D);
    transpose_kernel<<<dim3(KV_D / 32, D_MODEL / 32), dim3(32, 8)>>>(wv, wvT, D_MODEL, KV_D);
    transpose_kernel<<<dim3(D_MODEL / 32, D_MODEL / 32), dim3(32, 8)>>>(wo, woT, D_MODEL, D_MODEL);

    gemm_bf16x3<<<dim3(D_MODEL / 128, S_LEN / 128), 256, GM_SMEM>>>(x, wqT, q, S_LEN, D_MODEL, D_MODEL);
    gemm_bf16x3<<<dim3(KV_D / 128, S_LEN / 128), 256, GM_SMEM>>>(x, wkT, k, S_LEN, KV_D, D_MODEL);
    gemm_bf16x3<<<dim3(KV_D / 128, S_LEN / 128), 256, GM_SMEM>>>(x, wvT, v, S_LEN, KV_D, D_MODEL);

    {
        int totq = S_LEN * NH * 64;
        rope_kernel<<<(totq + 255) / 256, 256>>>(q, cosp, sinp, NH, totq);
        int totk = S_LEN * NG * 64;
        rope_kernel<<<(totk + 255) / 256, 256>>>(k, cosp, sinp, NG, totk);
    }

    flash_attn_mma<<<dim3(S_LEN / 128, NH), 256, FB_SMEM>>>(q, k, v, ctx);

    gemm_bf16x3<<<dim3(D_MODEL / 128, S_LEN / 128), 256, GM_SMEM>>>(ctx, woT, out, S_LEN, D_MODEL, D_MODEL);
}

// round 6
// speedup vs baseline: 3.4573x; 1.0384x over previous
#include <cuda_runtime.h>
#include <cuda_bf16.h>
#include <cstdint>

// Problem constants
#define S_LEN 4096
#define D_MODEL 2048
#define NH 16
#define NG 4
#define HD 128
#define KV_D (NG * HD)          // 512
#define SOFTMAX_SCALE 0.08838834764831845f  // 1/sqrt(128)

// fp32 scratch
__device__ float g_q[S_LEN * D_MODEL];
__device__ float g_k[S_LEN * KV_D];
__device__ float g_v[S_LEN * KV_D];
__device__ float g_ctx[S_LEN * D_MODEL];

// pre-split bf16 planes
__device__ __nv_bfloat16 g_xhi[S_LEN * D_MODEL];
__device__ __nv_bfloat16 g_xlo[S_LEN * D_MODEL];
__device__ __nv_bfloat16 g_ctxhi[S_LEN * D_MODEL];
__device__ __nv_bfloat16 g_ctxlo[S_LEN * D_MODEL];
__device__ __nv_bfloat16 g_wqThi[D_MODEL * D_MODEL];
__device__ __nv_bfloat16 g_wqTlo[D_MODEL * D_MODEL];
__device__ __nv_bfloat16 g_wkThi[KV_D * D_MODEL];
__device__ __nv_bfloat16 g_wkTlo[KV_D * D_MODEL];
__device__ __nv_bfloat16 g_wvThi[KV_D * D_MODEL];
__device__ __nv_bfloat16 g_wvTlo[KV_D * D_MODEL];
__device__ __nv_bfloat16 g_woThi[D_MODEL * D_MODEL];
__device__ __nv_bfloat16 g_woTlo[D_MODEL * D_MODEL];

// ---------------------------------------------------------------------------
// Helpers
// ---------------------------------------------------------------------------
__device__ __forceinline__ uint32_t smem_to_u32(const void* p) {
    uint32_t a;
    asm("{ .reg .u64 t; cvta.to.shared.u64 t, %1; cvt.u32.u64 %0, t; }"
        : "=r"(a) : "l"(p));
    return a;
}

__device__ __forceinline__ void cp_async16(uint32_t smem_addr, const void* gptr) {
    asm volatile("cp.async.cg.shared.global [%0], [%1], 16;" :: "r"(smem_addr), "l"(gptr));
}
__device__ __forceinline__ void cp_async_commit() {
    asm volatile("cp.async.commit_group;" ::: "memory");
}
template <int N>
__device__ __forceinline__ void cp_async_wait() {
    asm volatile("cp.async.wait_group %0;" :: "n"(N) : "memory");
}

__device__ __forceinline__ uint32_t pack_bf16(float x, float y) {
    uint32_t r;
    asm("cvt.rn.bf16x2.f32 %0, %1, %2;" : "=r"(r) : "f"(y), "f"(x));
    return r;
}
__device__ __forceinline__ float bf16lo_f32(uint32_t h) { return __uint_as_float(h << 16); }
__device__ __forceinline__ float bf16hi_f32(uint32_t h) { return __uint_as_float(h & 0xffff0000u); }

__device__ __forceinline__ void split_bf16(float2 f, uint32_t& hi, uint32_t& lo) {
    hi = pack_bf16(f.x, f.y);
    float rx = f.x - bf16lo_f32(hi);
    float ry = f.y - bf16hi_f32(hi);
    lo = pack_bf16(rx, ry);
}

__device__ __forceinline__ void mma_bf16(float* c, const uint32_t* a, const uint32_t* b) {
    asm volatile(
        "mma.sync.aligned.m16n8k16.row.col.f32.bf16.bf16.f32 "
        "{%0,%1,%2,%3}, {%4,%5,%6,%7}, {%8,%9}, {%0,%1,%2,%3};"
        : "+f"(c[0]), "+f"(c[1]), "+f"(c[2]), "+f"(c[3])
        : "r"(a[0]), "r"(a[1]), "r"(a[2]), "r"(a[3]), "r"(b[0]), "r"(b[1]));
}

__device__ __forceinline__ void ldsm_x4(uint32_t* r, uint32_t addr) {
    asm volatile("ldmatrix.sync.aligned.m8n8.x4.shared.b16 {%0,%1,%2,%3}, [%4];"
        : "=r"(r[0]), "=r"(r[1]), "=r"(r[2]), "=r"(r[3]) : "r"(addr));
}
__device__ __forceinline__ void ldsm_x2(uint32_t* r, uint32_t addr) {
    asm volatile("ldmatrix.sync.aligned.m8n8.x2.shared.b16 {%0,%1}, [%2];"
        : "=r"(r[0]), "=r"(r[1]) : "r"(addr));
}

// ---------------------------------------------------------------------------
// Split kernels (fp32 -> bf16 hi/lo planes)
// ---------------------------------------------------------------------------
__global__ void split_kernel(const float* __restrict__ in,
                             __nv_bfloat16* __restrict__ hi,
                             __nv_bfloat16* __restrict__ lo,
                             int n4, float scale) {
    int idx = blockIdx.x * blockDim.x + threadIdx.x;
    if (idx >= n4) return;
    float4 v = ((const float4*)in)[idx];
    v.x *= scale; v.y *= scale; v.z *= scale; v.w *= scale;
    uint32_t h01, l01, h23, l23;
    split_bf16(make_float2(v.x, v.y), h01, l01);
    split_bf16(make_float2(v.z, v.w), h23, l23);
    ((uint2*)hi)[idx] = make_uint2(h01, h23);
    ((uint2*)lo)[idx] = make_uint2(l01, l23);
}

// transpose + split: out[C,R] (bf16 hi/lo) = in[R,C] (fp32)
__global__ void transpose_split_kernel(const float* __restrict__ in,
                                       __nv_bfloat16* __restrict__ hiT,
                                       __nv_bfloat16* __restrict__ loT,
                                       int R, int C) {
    __shared__ float t[32][33];
    int c0 = blockIdx.x * 32, r0 = blockIdx.y * 32;
    int x = threadIdx.x, y = threadIdx.y;  // 32 x 8
#pragma unroll
    for (int i = y; i < 32; i += 8) t[i][x] = in[(size_t)(r0 + i) * C + c0 + x];
    __syncthreads();
#pragma unroll
    for (int i = y; i < 32; i += 8) {
        float v = t[x][i];
        __nv_bfloat16 h = __float2bfloat16(v);
        __nv_bfloat16 l = __float2bfloat16(v - __bfloat162float(h));
        size_t o = (size_t)(c0 + i) * R + r0 + x;
        hiT[o] = h;
        loT[o] = l;
    }
}

// ---------------------------------------------------------------------------
// GEMM on pre-split bf16 planes: C[M,N] = (Ahi+Alo)[M,K] @ (Bhi+Blo)[N,K]^T
// 128x128 CTA tile, BK=32, 8 warps (2x4), warp 64x32, 3-stage cp.async,
// ldmatrix fragments, 3-term compensated accumulation.
// ---------------------------------------------------------------------------
#define SROWB 56                      // bf16 row stride (112 B, conflict-free ldsm)
#define PLANE_B (128 * SROWB * 2)     // 14336 B per plane
#define GSTAGE_B (4 * PLANE_B)        // Ahi,Alo,Bhi,Blo = 57344 B
#define GM_NST 3
#define GM_SMEM (GM_NST * GSTAGE_B)   // 172032 B

__global__ __launch_bounds__(256, 1) void gemm_bf16p(
        const __nv_bfloat16* __restrict__ Ahi, const __nv_bfloat16* __restrict__ Alo,
        const __nv_bfloat16* __restrict__ Bhi, const __nv_bfloat16* __restrict__ Blo,
        float* __restrict__ C, int M, int N, int K) {
    extern __shared__ char sm[];
    const uint32_t smem_u32 = smem_to_u32(sm);

    const int tid = threadIdx.x;
    const int wid = tid >> 5;
    const int lane = tid & 31;
    const int lr = lane & 7;
    const int lb8 = (lane >> 3) & 1;
    const int lb16 = (lane >> 4) & 1;
    const int wm = wid >> 2;
    const int wn = wid & 3;
    const int m0 = blockIdx.y * 128;
    const int n0 = blockIdx.x * 128;
    const int NS = K >> 5;

    const __nv_bfloat16* srcs[4] = {Ahi, Alo, Bhi, Blo};

    auto load_stage = [&](int s, int buf) {
        const int k0 = s << 5;
#pragma unroll
        for (int i = 0; i < 8; i++) {
            int c = tid + i * 256;        // 0..2047
            int plane = c >> 9;           // 0..3
            int idx = c & 511;
            int row = idx >> 2;           // 0..127
            int ch = idx & 3;             // 16B chunk within 64B row
            int grow = (plane < 2 ? m0 : n0) + row;
            const __nv_bfloat16* g = srcs[plane] + (size_t)grow * K + k0 + ch * 8;
            uint32_t dst = smem_u32 + buf * GSTAGE_B + plane * PLANE_B +
                           (row * SROWB + ch * 8) * 2;
            cp_async16(dst, g);
        }
    };

    float acc[4][4][4];
#pragma unroll
    for (int m = 0; m < 4; m++)
#pragma unroll
        for (int n = 0; n < 4; n++)
#pragma unroll
            for (int i = 0; i < 4; i++) acc[m][n][i] = 0.0f;

    load_stage(0, 0); cp_async_commit();
    load_stage(1, 1); cp_async_commit();
    load_stage(2, 2); cp_async_commit();

    // per-thread ldmatrix base offsets (within a stage buffer)
    const uint32_t a_off = ((wm * 64 + lr + lb8 * 8) * SROWB + lb16 * 8) * 2;
    const uint32_t b_off = 2 * PLANE_B + ((wn * 32 + lr + lb16 * 8) * SROWB + lb8 * 8) * 2;

    for (int s = 0; s < NS; s++) {
        const int buf = s % GM_NST;
        cp_async_wait<GM_NST - 1>();
        __syncthreads();

        const uint32_t base = smem_u32 + buf * GSTAGE_B;

#pragma unroll
        for (int ks = 0; ks < 32; ks += 16) {
            uint32_t bhi[2][4], blo[2][4];
#pragma unroll
            for (int np = 0; np < 2; np++) {
                uint32_t addr = base + b_off + (np * 16 * SROWB + ks) * 2;
                ldsm_x4(bhi[np], addr);
                ldsm_x4(blo[np], addr + PLANE_B);
            }
#pragma unroll
            for (int m = 0; m < 4; m++) {
                uint32_t ahi[4], alo[4];
                uint32_t addr = base + a_off + (m * 16 * SROWB + ks) * 2;
                ldsm_x4(ahi, addr);
                ldsm_x4(alo, addr + PLANE_B);
#pragma unroll
                for (int n = 0; n < 4; n++) {
                    const uint32_t* bh = &bhi[n >> 1][(n & 1) * 2];
                    const uint32_t* bl = &blo[n >> 1][(n & 1) * 2];
                    mma_bf16(acc[m][n], ahi, bh);
                    mma_bf16(acc[m][n], ahi, bl);
                    mma_bf16(acc[m][n], alo, bh);
                }
            }
        }

        __syncthreads();
        if (s + GM_NST < NS) load_stage(s + GM_NST, buf);
        cp_async_commit();
    }

    const int g = lane >> 2;
    const int tig = lane & 3;
#pragma unroll
    for (int m = 0; m < 4; m++) {
        int r0 = m0 + wm * 64 + m * 16 + g;
        int r1 = r0 + 8;
#pragma unroll
        for (int n = 0; n < 4; n++) {
            int col = n0 + wn * 32 + n * 8 + tig * 2;
            *(float2*)(C + (size_t)r0 * N + col) = make_float2(acc[m][n][0], acc[m][n][1]);
            *(float2*)(C + (size_t)r1 * N + col) = make_float2(acc[m][n][2], acc[m][n][3]);
        }
    }
}

// ---------------------------------------------------------------------------
// RoPE, in place.
// ---------------------------------------------------------------------------
__global__ void rope_kernel(float* __restrict__ t,
                            const float* __restrict__ cosp,
                            const float* __restrict__ sinp,
                            int nh, int total) {
    int idx = blockIdx.x * blockDim.x + threadIdx.x;
    if (idx >= total) return;
    int d = idx & 63;
    int h = (idx >> 6) % nh;
    int s = idx / (64 * nh);
    float* row = t + (size_t)s * (nh * 128) + h * 128;
    float c1 = cosp[s * 128 + d];
    float s1 = sinp[s * 128 + d];
    float c2 = cosp[s * 128 + d + 64];
    float s2 = sinp[s * 128 + d + 64];
    float a = row[d];
    float b = row[d + 64];
    row[d]      = a * c1 - b * s1;
    row[d + 64] = b * c2 + a * s2;
}

// ---------------------------------------------------------------------------
// Flash attention on mma.sync (bf16x3 compensated), causal. (round-5 version)
// ---------------------------------------------------------------------------
#define QLD 136
#define VLD 72
#define OFF_QHI 0
#define OFF_QLO 34816
#define OFF_KHI 69632
#define OFF_KLO 87040
#define OFF_VTHI 104448
#define OFF_VTLO 122880
#define FB_SMEM 141312

__global__ __launch_bounds__(256, 1) void flash_attn_mma(const float* __restrict__ Q,
                                                         const float* __restrict__ K,
                                                         const float* __restrict__ V,
                                                         float* __restrict__ O) {
    extern __shared__ char sm[];
    const uint32_t smem_u32 = smem_to_u32(sm);

    const int qt = blockIdx.x;
    const int h = blockIdx.y;
    const int kvg = h >> 2;
    const int tid = threadIdx.x;
    const int w = tid >> 5;
    const int lane = tid & 31;
    const int lg = lane >> 2;
    const int tig = lane & 3;
    const int q0 = qt * 128;
    const int qb = w * 16;

    for (int c = tid; c < 128 * 32; c += 256) {
        int row = c >> 5;
        int col4 = (c & 31) << 2;
        float4 v = *(const float4*)(Q + (size_t)(q0 + row) * D_MODEL + h * HD + col4);
        v.x *= SOFTMAX_SCALE; v.y *= SOFTMAX_SCALE; v.z *= SOFTMAX_SCALE; v.w *= SOFTMAX_SCALE;
        uint32_t h01, l01, h23, l23;
        split_bf16(make_float2(v.x, v.y), h01, l01);
        split_bf16(make_float2(v.z, v.w), h23, l23);
        uint32_t off = (row * QLD + col4) * 2;
        *(uint32_t*)(sm + OFF_QHI + off) = h01;
        *(uint32_t*)(sm + OFF_QHI + off + 4) = h23;
        *(uint32_t*)(sm + OFF_QLO + off) = l01;
        *(uint32_t*)(sm + OFF_QLO + off + 4) = l23;
    }

    const int lr = lane & 7;
    const int lb8 = (lane >> 3) & 1;
    const int lb16 = (lane >> 4) & 1;
    const uint32_t qa_hi = smem_u32 + OFF_QHI + ((qb + lr + lb8 * 8) * QLD + lb16 * 8) * 2;
    const uint32_t qa_lo = qa_hi + (OFF_QLO - OFF_QHI);
    const uint32_t kb_hi = smem_u32 + OFF_KHI + (lr * QLD + lb8 * 8) * 2;
    const uint32_t vb_hi = smem_u32 + OFF_VTHI + (lr * VLD + lb8 * 8) * 2;

    float m0 = -1e30f, m1 = -1e30f, l0 = 0.0f, l1 = 0.0f;
    float oacc[16][4];
#pragma unroll
    for (int nt = 0; nt < 16; nt++)
#pragma unroll
        for (int j = 0; j < 4; j++) oacc[nt][j] = 0.0f;

    const int njt = 2 * qt + 2;
    for (int jt = 0; jt < njt; jt++) {
        __syncthreads();
        for (int c = tid; c < 2048; c += 256) {
            int row = c >> 5;
            int col4 = (c & 31) << 2;
            float4 v = *(const float4*)(K + (size_t)(jt * 64 + row) * KV_D + kvg * HD + col4);
            uint32_t h01, l01, h23, l23;
            split_bf16(make_float2(v.x, v.y), h01, l01);
            split_bf16(make_float2(v.z, v.w), h23, l23);
            uint32_t off = (row * QLD + col4) * 2;
            *(uint32_t*)(sm + OFF_KHI + off) = h01;
            *(uint32_t*)(sm + OFF_KHI + off + 4) = h23;
            *(uint32_t*)(sm + OFF_KLO + off) = l01;
            *(uint32_t*)(sm + OFF_KLO + off + 4) = l23;
        }
        for (int c = tid; c < 2048; c += 256) {
            int row = c & 63;
            int col = (c >> 6) << 2;
            float4 v = *(const float4*)(V + (size_t)(jt * 64 + row) * KV_D + kvg * HD + col);
            float vv[4] = {v.x, v.y, v.z, v.w};
#pragma unroll
            for (int j = 0; j < 4; j++) {
                __nv_bfloat16 hb = __float2bfloat16(vv[j]);
                float r = vv[j] - __bfloat162float(hb);
                __nv_bfloat16 lb = __float2bfloat16(r);
                uint32_t off = ((col + j) * VLD + row) * 2;
                *(__nv_bfloat16*)(sm + OFF_VTHI + off) = hb;
                *(__nv_bfloat16*)(sm + OFF_VTLO + off) = lb;
            }
        }
        __syncthreads();

        if (jt * 64 > q0 + qb + 15) continue;

        float sacc[8][4];
#pragma unroll
        for (int nt = 0; nt < 8; nt++)
#pragma unroll
            for (int j = 0; j < 4; j++) sacc[nt][j] = 0.0f;

#pragma unroll
        for (int kc = 0; kc < 8; kc++) {
            uint32_t qhi[4], qlo[4];
            ldsm_x4(qhi, qa_hi + kc * 32);
            ldsm_x4(qlo, qa_lo + kc * 32);
#pragma unroll
            for (int nt = 0; nt < 8; nt++) {
                uint32_t khi[2], klo[2];
                uint32_t kaddr = kb_hi + nt * (8 * QLD * 2) + kc * 32;
                ldsm_x2(khi, kaddr);
                ldsm_x2(klo, kaddr + (OFF_KLO - OFF_KHI));
                mma_bf16(sacc[nt], qhi, khi);
                mma_bf16(sacc[nt], qhi, klo);
                mma_bf16(sacc[nt], qlo, khi);
            }
        }

        if (jt * 64 + 63 > q0 + qb) {
#pragma unroll
            for (int nt = 0; nt < 8; nt++)
#pragma unroll
                for (int j = 0; j < 4; j++) {
                    int gj = jt * 64 + nt * 8 + tig * 2 + (j & 1);
                    int gi = q0 + qb + lg + ((j >> 1) << 3);
                    if (gj > gi) sacc[nt][j] = -1e30f;
                }
        }

        float cur0 = -1e30f, cur1 = -1e30f;
#pragma unroll
        for (int nt = 0; nt < 8; nt++) {
            cur0 = fmaxf(cur0, fmaxf(sacc[nt][0], sacc[nt][1]));
            cur1 = fmaxf(cur1, fmaxf(sacc[nt][2], sacc[nt][3]));
        }
        cur0 = fmaxf(cur0, __shfl_xor_sync(0xffffffffu, cur0, 1));
        cur0 = fmaxf(cur0, __shfl_xor_sync(0xffffffffu, cur0, 2));
        cur1 = fmaxf(cur1, __shfl_xor_sync(0xffffffffu, cur1, 1));
        cur1 = fmaxf(cur1, __shfl_xor_sync(0xffffffffu, cur1, 2));

        float mn0 = fmaxf(m0, cur0), mn1 = fmaxf(m1, cur1);
        float alpha0 = __expf(m0 - mn0), alpha1 = __expf(m1 - mn1);
        m0 = mn0; m1 = mn1;

        float rs0 = 0.0f, rs1 = 0.0f;
#pragma unroll
        for (int nt = 0; nt < 8; nt++) {
            sacc[nt][0] = __expf(sacc[nt][0] - mn0);
            sacc[nt][1] = __expf(sacc[nt][1] - mn0);
            sacc[nt][2] = __expf(sacc[nt][2] - mn1);
            sacc[nt][3] = __expf(sacc[nt][3] - mn1);
            rs0 += sacc[nt][0] + sacc[nt][1];
            rs1 += sacc[nt][2] + sacc[nt][3];
        }
        rs0 += __shfl_xor_sync(0xffffffffu, rs0, 1);
        rs0 += __shfl_xor_sync(0xffffffffu, rs0, 2);
        rs1 += __shfl_xor_sync(0xffffffffu, rs1, 1);
        rs1 += __shfl_xor_sync(0xffffffffu, rs1, 2);
        l0 = l0 * alpha0 + rs0;
        l1 = l1 * alpha1 + rs1;

#pragma unroll
        for (int nt = 0; nt < 16; nt++) {
            oacc[nt][0] *= alpha0;
            oacc[nt][1] *= alpha0;
            oacc[nt][2] *= alpha1;
            oacc[nt][3] *= alpha1;
        }

#pragma unroll
        for (int kc = 0; kc < 4; kc++) {
            uint32_t ahi[4], alo[4];
            split_bf16(make_float2(sacc[2 * kc][0], sacc[2 * kc][1]), ahi[0], alo[0]);
            split_bf16(make_float2(sacc[2 * kc][2], sacc[2 * kc][3]), ahi[1], alo[1]);
            split_bf16(make_float2(sacc[2 * kc + 1][0], sacc[2 * kc + 1][1]), ahi[2], alo[2]);
            split_bf16(make_float2(sacc[2 * kc + 1][2], sacc[2 * kc + 1][3]), ahi[3], alo[3]);
#pragma unroll
            for (int nt = 0; nt < 16; nt++) {
                uint32_t vhi[2], vlo[2];
                uint32_t vaddr = vb_hi + nt * (8 * VLD * 2) + kc * 32;
                ldsm_x2(vhi, vaddr);
                ldsm_x2(vlo, vaddr + (OFF_VTLO - OFF_VTHI));
                mma_bf16(oacc[nt], ahi, vhi);
                mma_bf16(oacc[nt], alo, vhi);
                mma_bf16(oacc[nt], ahi, vlo);
            }
        }
    }

    float inv0 = 1.0f / l0;
    float inv1 = 1.0f / l1;
    int row0 = q0 + qb + lg;
    int row1 = row0 + 8;
#pragma unroll
    for (int nt = 0; nt < 16; nt++) {
        int col = h * HD + nt * 8 + tig * 2;
        *(float2*)(O + (size_t)row0 * D_MODEL + col) =
            make_float2(oacc[nt][0] * inv0, oacc[nt][1] * inv0);
        *(float2*)(O + (size_t)row1 * D_MODEL + col) =
            make_float2(oacc[nt][2] * inv1, oacc[nt][3] * inv1);
    }
}

// ---------------------------------------------------------------------------
extern "C" void kernel_launch(void* const* d_in, const int* in_sizes, int n_in,
                              void* d_out, int out_size) {
    const float* x    = (const float*)d_in[0];
    const float* wq   = (const float*)d_in[2];
    const float* wk   = (const float*)d_in[3];
    const float* wv   = (const float*)d_in[4];
    const float* wo   = (const float*)d_in[5];
    const float* cosp = (const float*)d_in[6];
    const float* sinp = (const float*)d_in[7];
    float* out = (float*)d_out;

    float *q, *k, *v, *ctx;
    cudaGetSymbolAddress((void**)&q, g_q);
    cudaGetSymbolAddress((void**)&k, g_k);
    cudaGetSymbolAddress((void**)&v, g_v);
    cudaGetSymbolAddress((void**)&ctx, g_ctx);
    __nv_bfloat16 *xhi, *xlo, *ctxhi, *ctxlo;
    __nv_bfloat16 *wqThi, *wqTlo, *wkThi, *wkTlo, *wvThi, *wvTlo, *woThi, *woTlo;
    cudaGetSymbolAddress((void**)&xhi, g_xhi);
    cudaGetSymbolAddress((void**)&xlo, g_xlo);
    cudaGetSymbolAddress((void**)&ctxhi, g_ctxhi);
    cudaGetSymbolAddress((void**)&ctxlo, g_ctxlo);
    cudaGetSymbolAddress((void**)&wqThi, g_wqThi);
    cudaGetSymbolAddress((void**)&wqTlo, g_wqTlo);
    cudaGetSymbolAddress((void**)&wkThi, g_wkThi);
    cudaGetSymbolAddress((void**)&wkTlo, g_wkTlo);
    cudaGetSymbolAddress((void**)&wvThi, g_wvThi);
    cudaGetSymbolAddress((void**)&wvTlo, g_wvTlo);
    cudaGetSymbolAddress((void**)&woThi, g_woThi);
    cudaGetSymbolAddress((void**)&woTlo, g_woTlo);

    cudaFuncSetAttribute(gemm_bf16p, cudaFuncAttributeMaxDynamicSharedMemorySize, GM_SMEM);
    cudaFuncSetAttribute(flash_attn_mma, cudaFuncAttributeMaxDynamicSharedMemorySize, FB_SMEM);

    // Pre-split inputs
    {
        int n4 = S_LEN * D_MODEL / 4;
        split_kernel<<<(n4 + 255) / 256, 256>>>(x, xhi, xlo, n4, 1.0f);
    }
    transpose_split_kernel<<<dim3(D_MODEL / 32, D_MODEL / 32), dim3(32, 8)>>>(wq, wqThi, wqTlo, D_MODEL, D_MODEL);
    transpose_split_kernel<<<dim3(KV_D / 32, D_MODEL / 32), dim3(32, 8)>>>(wk, wkThi, wkTlo, D_MODEL, KV_D);
    transpose_split_kernel<<<dim3(KV_D / 32, D_MODEL / 32), dim3(32, 8)>>>(wv, wvThi, wvTlo, D_MODEL, KV_D);
    transpose_split_kernel<<<dim3(D_MODEL / 32, D_MODEL / 32), dim3(32, 8)>>>(wo, woThi, woTlo, D_MODEL, D_MODEL);

    // Projections
    gemm_bf16p<<<dim3(D_MODEL / 128, S_LEN / 128), 256, GM_SMEM>>>(xhi, xlo, wqThi, wqTlo, q, S_LEN, D_MODEL, D_MODEL);
    gemm_bf16p<<<dim3(KV_D / 128, S_LEN / 128), 256, GM_SMEM>>>(xhi, xlo, wkThi, wkTlo, k, S_LEN, KV_D, D_MODEL);
    gemm_bf16p<<<dim3(KV_D / 128, S_LEN / 128), 256, GM_SMEM>>>(xhi, xlo, wvThi, wvTlo, v, S_LEN, KV_D, D_MODEL);

    // RoPE
    {
        int totq = S_LEN * NH * 64;
        rope_kernel<<<(totq + 255) / 256, 256>>>(q, cosp, sinp, NH, totq);
        int totk = S_LEN * NG * 64;
        rope_kernel<<<(totk + 255) / 256, 256>>>(k, cosp, sinp, NG, totk);
    }

    // Flash attention
    flash_attn_mma<<<dim3(S_LEN / 128, NH), 256, FB_SMEM>>>(q, k, v, ctx);

    // Output projection (split ctx first)
    {
        int n4 = S_LEN * D_MODEL / 4;
        split_kernel<<<(n4 + 255) / 256, 256>>>(ctx, ctxhi, ctxlo, n4, 1.0f);
    }
    gemm_bf16p<<<dim3(D_MODEL / 128, S_LEN / 128), 256, GM_SMEM>>>(ctxhi, ctxlo, woThi, woTlo, out, S_LEN, D_MODEL, D_MODEL);
}

// round 7
// speedup vs baseline: 3.9870x; 1.1532x over previous
#include <cuda_runtime.h>
#include <cuda_bf16.h>
#include <cstdint>

// Problem constants
#define S_LEN 4096
#define D_MODEL 2048
#define NH 16
#define NG 4
#define HD 128
#define KV_D (NG * HD)          // 512
#define SOFTMAX_SCALE 0.08838834764831845f  // 1/sqrt(128)

// fp32 scratch (gemm outputs)
__device__ float g_q[S_LEN * D_MODEL];
__device__ float g_k[S_LEN * KV_D];
__device__ float g_v[S_LEN * KV_D];

// bf16 hi/lo planes
__device__ __nv_bfloat16 g_xhi[S_LEN * D_MODEL];
__device__ __nv_bfloat16 g_xlo[S_LEN * D_MODEL];
__device__ __nv_bfloat16 g_qhi[S_LEN * D_MODEL];
__device__ __nv_bfloat16 g_qlo[S_LEN * D_MODEL];
__device__ __nv_bfloat16 g_khi[S_LEN * KV_D];
__device__ __nv_bfloat16 g_klo[S_LEN * KV_D];
__device__ __nv_bfloat16 g_vhi[S_LEN * KV_D];
__device__ __nv_bfloat16 g_vlo[S_LEN * KV_D];
__device__ __nv_bfloat16 g_ctxhi[S_LEN * D_MODEL];
__device__ __nv_bfloat16 g_ctxlo[S_LEN * D_MODEL];
__device__ __nv_bfloat16 g_wqThi[D_MODEL * D_MODEL];
__device__ __nv_bfloat16 g_wqTlo[D_MODEL * D_MODEL];
__device__ __nv_bfloat16 g_wkThi[KV_D * D_MODEL];
__device__ __nv_bfloat16 g_wkTlo[KV_D * D_MODEL];
__device__ __nv_bfloat16 g_wvThi[KV_D * D_MODEL];
__device__ __nv_bfloat16 g_wvTlo[KV_D * D_MODEL];
__device__ __nv_bfloat16 g_woThi[D_MODEL * D_MODEL];
__device__ __nv_bfloat16 g_woTlo[D_MODEL * D_MODEL];

// ---------------------------------------------------------------------------
// Helpers
// ---------------------------------------------------------------------------
__device__ __forceinline__ uint32_t smem_to_u32(const void* p) {
    uint32_t a;
    asm("{ .reg .u64 t; cvta.to.shared.u64 t, %1; cvt.u32.u64 %0, t; }"
        : "=r"(a) : "l"(p));
    return a;
}

__device__ __forceinline__ void cp_async16(uint32_t smem_addr, const void* gptr) {
    asm volatile("cp.async.cg.shared.global [%0], [%1], 16;" :: "r"(smem_addr), "l"(gptr));
}
__device__ __forceinline__ void cp_async_commit() {
    asm volatile("cp.async.commit_group;" ::: "memory");
}
template <int N>
__device__ __forceinline__ void cp_async_wait() {
    asm volatile("cp.async.wait_group %0;" :: "n"(N) : "memory");
}

__device__ __forceinline__ uint32_t pack_bf16(float x, float y) {
    uint32_t r;
    asm("cvt.rn.bf16x2.f32 %0, %1, %2;" : "=r"(r) : "f"(y), "f"(x));
    return r;
}
__device__ __forceinline__ float bf16lo_f32(uint32_t h) { return __uint_as_float(h << 16); }
__device__ __forceinline__ float bf16hi_f32(uint32_t h) { return __uint_as_float(h & 0xffff0000u); }

__device__ __forceinline__ void split_bf16(float2 f, uint32_t& hi, uint32_t& lo) {
    hi = pack_bf16(f.x, f.y);
    float rx = f.x - bf16lo_f32(hi);
    float ry = f.y - bf16hi_f32(hi);
    lo = pack_bf16(rx, ry);
}

__device__ __forceinline__ void mma_bf16(float* c, const uint32_t* a, const uint32_t* b) {
    asm volatile(
        "mma.sync.aligned.m16n8k16.row.col.f32.bf16.bf16.f32 "
        "{%0,%1,%2,%3}, {%4,%5,%6,%7}, {%8,%9}, {%0,%1,%2,%3};"
        : "+f"(c[0]), "+f"(c[1]), "+f"(c[2]), "+f"(c[3])
        : "r"(a[0]), "r"(a[1]), "r"(a[2]), "r"(a[3]), "r"(b[0]), "r"(b[1]));
}

__device__ __forceinline__ void ldsm_x4(uint32_t* r, uint32_t addr) {
    asm volatile("ldmatrix.sync.aligned.m8n8.x4.shared.b16 {%0,%1,%2,%3}, [%4];"
        : "=r"(r[0]), "=r"(r[1]), "=r"(r[2]), "=r"(r[3]) : "r"(addr));
}
__device__ __forceinline__ void ldsm_x4t(uint32_t* r, uint32_t addr) {
    asm volatile("ldmatrix.sync.aligned.m8n8.x4.trans.shared.b16 {%0,%1,%2,%3}, [%4];"
        : "=r"(r[0]), "=r"(r[1]), "=r"(r[2]), "=r"(r[3]) : "r"(addr));
}

// ---------------------------------------------------------------------------
// Split kernels
// ---------------------------------------------------------------------------
__global__ void split_kernel(const float* __restrict__ in,
                             __nv_bfloat16* __restrict__ hi,
                             __nv_bfloat16* __restrict__ lo,
                             int n4) {
    int idx = blockIdx.x * blockDim.x + threadIdx.x;
    if (idx >= n4) return;
    float4 v = ((const float4*)in)[idx];
    uint32_t h01, l01, h23, l23;
    split_bf16(make_float2(v.x, v.y), h01, l01);
    split_bf16(make_float2(v.z, v.w), h23, l23);
    ((uint2*)hi)[idx] = make_uint2(h01, h23);
    ((uint2*)lo)[idx] = make_uint2(l01, l23);
}

// rope + scale + split: reads fp32 [S, nh*128], writes bf16 hi/lo planes
__global__ void rope_split_kernel(const float* __restrict__ t,
                                  const float* __restrict__ cosp,
                                  const float* __restrict__ sinp,
                                  __nv_bfloat16* __restrict__ hi,
                                  __nv_bfloat16* __restrict__ lo,
                                  int nh, int total, float scale) {
    int idx = blockIdx.x * blockDim.x + threadIdx.x;
    if (idx >= total) return;
    int i = idx & 31;
    int h = (idx >> 5) % nh;
    int s = idx / (32 * nh);
    int d0 = 2 * i;
    const float* row = t + (size_t)s * (nh * 128) + h * 128;
    float a0 = row[d0], a1 = row[d0 + 1];
    float b0 = row[d0 + 64], b1 = row[d0 + 65];
    float c0 = cosp[s * 128 + d0], c1 = cosp[s * 128 + d0 + 1];
    float s0 = sinp[s * 128 + d0], s1 = sinp[s * 128 + d0 + 1];
    float c2 = cosp[s * 128 + d0 + 64], c3 = cosp[s * 128 + d0 + 65];
    float s2 = sinp[s * 128 + d0 + 64], s3 = sinp[s * 128 + d0 + 65];
    float o0 = (a0 * c0 - b0 * s0) * scale;
    float o1 = (a1 * c1 - b1 * s1) * scale;
    float o2 = (b0 * c2 + a0 * s2) * scale;
    float o3 = (b1 * c3 + a1 * s3) * scale;
    uint32_t h01, l01, h23, l23;
    split_bf16(make_float2(o0, o1), h01, l01);
    split_bf16(make_float2(o2, o3), h23, l23);
    size_t base = (size_t)s * (nh * 128) + h * 128;
    *(uint32_t*)&hi[base + d0] = h01;
    *(uint32_t*)&lo[base + d0] = l01;
    *(uint32_t*)&hi[base + d0 + 64] = h23;
    *(uint32_t*)&lo[base + d0 + 64] = l23;
}

// transpose + split: out[C,R] (bf16 hi/lo) = in[R,C] (fp32)
__global__ void transpose_split_kernel(const float* __restrict__ in,
                                       __nv_bfloat16* __restrict__ hiT,
                                       __nv_bfloat16* __restrict__ loT,
                                       int R, int C) {
    __shared__ float t[32][33];
    int c0 = blockIdx.x * 32, r0 = blockIdx.y * 32;
    int x = threadIdx.x, y = threadIdx.y;
#pragma unroll
    for (int i = y; i < 32; i += 8) t[i][x] = in[(size_t)(r0 + i) * C + c0 + x];
    __syncthreads();
#pragma unroll
    for (int i = y; i < 32; i += 8) {
        float v = t[x][i];
        __nv_bfloat16 h = __float2bfloat16(v);
        __nv_bfloat16 l = __float2bfloat16(v - __bfloat162float(h));
        size_t o = (size_t)(c0 + i) * R + r0 + x;
        hiT[o] = h;
        loT[o] = l;
    }
}

// ---------------------------------------------------------------------------
// GEMM on pre-split bf16 planes (round-6 version, unchanged)
// ---------------------------------------------------------------------------
#define SROWB 56
#define PLANE_B (128 * SROWB * 2)
#define GSTAGE_B (4 * PLANE_B)
#define GM_NST 3
#define GM_SMEM (GM_NST * GSTAGE_B)

__global__ __launch_bounds__(256, 1) void gemm_bf16p(
        const __nv_bfloat16* __restrict__ Ahi, const __nv_bfloat16* __restrict__ Alo,
        const __nv_bfloat16* __restrict__ Bhi, const __nv_bfloat16* __restrict__ Blo,
        float* __restrict__ C, int M, int N, int K) {
    extern __shared__ char sm[];
    const uint32_t smem_u32 = smem_to_u32(sm);

    const int tid = threadIdx.x;
    const int wid = tid >> 5;
    const int lane = tid & 31;
    const int lr = lane & 7;
    const int lb8 = (lane >> 3) & 1;
    const int lb16 = (lane >> 4) & 1;
    const int wm = wid >> 2;
    const int wn = wid & 3;
    const int m0 = blockIdx.y * 128;
    const int n0 = blockIdx.x * 128;
    const int NS = K >> 5;

    const __nv_bfloat16* srcs[4] = {Ahi, Alo, Bhi, Blo};

    auto load_stage = [&](int s, int buf) {
        const int k0 = s << 5;
#pragma unroll
        for (int i = 0; i < 8; i++) {
            int c = tid + i * 256;
            int plane = c >> 9;
            int idx = c & 511;
            int row = idx >> 2;
            int ch = idx & 3;
            int grow = (plane < 2 ? m0 : n0) + row;
            const __nv_bfloat16* g = srcs[plane] + (size_t)grow * K + k0 + ch * 8;
            uint32_t dst = smem_u32 + buf * GSTAGE_B + plane * PLANE_B +
                           (row * SROWB + ch * 8) * 2;
            cp_async16(dst, g);
        }
    };

    float acc[4][4][4];
#pragma unroll
    for (int m = 0; m < 4; m++)
#pragma unroll
        for (int n = 0; n < 4; n++)
#pragma unroll
            for (int i = 0; i < 4; i++) acc[m][n][i] = 0.0f;

    load_stage(0, 0); cp_async_commit();
    load_stage(1, 1); cp_async_commit();
    load_stage(2, 2); cp_async_commit();

    const uint32_t a_off = ((wm * 64 + lr + lb8 * 8) * SROWB + lb16 * 8) * 2;
    const uint32_t b_off = 2 * PLANE_B + ((wn * 32 + lr + lb16 * 8) * SROWB + lb8 * 8) * 2;

    for (int s = 0; s < NS; s++) {
        const int buf = s % GM_NST;
        cp_async_wait<GM_NST - 1>();
        __syncthreads();

        const uint32_t base = smem_u32 + buf * GSTAGE_B;

#pragma unroll
        for (int ks = 0; ks < 32; ks += 16) {
            uint32_t bhi[2][4], blo[2][4];
#pragma unroll
            for (int np = 0; np < 2; np++) {
                uint32_t addr = base + b_off + (np * 16 * SROWB + ks) * 2;
                ldsm_x4(bhi[np], addr);
                ldsm_x4(blo[np], addr + PLANE_B);
            }
#pragma unroll
            for (int m = 0; m < 4; m++) {
                uint32_t ahi[4], alo[4];
                uint32_t addr = base + a_off + (m * 16 * SROWB + ks) * 2;
                ldsm_x4(ahi, addr);
                ldsm_x4(alo, addr + PLANE_B);
#pragma unroll
                for (int n = 0; n < 4; n++) {
                    const uint32_t* bh = &bhi[n >> 1][(n & 1) * 2];
                    const uint32_t* bl = &blo[n >> 1][(n & 1) * 2];
                    mma_bf16(acc[m][n], ahi, bh);
                    mma_bf16(acc[m][n], ahi, bl);
                    mma_bf16(acc[m][n], alo, bh);
                }
            }
        }

        __syncthreads();
        if (s + GM_NST < NS) load_stage(s + GM_NST, buf);
        cp_async_commit();
    }

    const int g = lane >> 2;
    const int tig = lane & 3;
#pragma unroll
    for (int m = 0; m < 4; m++) {
        int r0 = m0 + wm * 64 + m * 16 + g;
        int r1 = r0 + 8;
#pragma unroll
        for (int n = 0; n < 4; n++) {
            int col = n0 + wn * 32 + n * 8 + tig * 2;
            *(float2*)(C + (size_t)r0 * N + col) = make_float2(acc[m][n][0], acc[m][n][1]);
            *(float2*)(C + (size_t)r1 * N + col) = make_float2(acc[m][n][2], acc[m][n][3]);
        }
    }
}

// ---------------------------------------------------------------------------
// Flash attention v2: pre-split bf16 planes, cp.async double-buffered KV,
// ldmatrix x4 (K) / x4.trans (V), ctx written as hi/lo planes.
// ---------------------------------------------------------------------------
#define QROW 136
#define FOFF_QLO 34816
#define FSTAGE0 69632
#define FSTAGE_B 69632
#define FKLO 17408
#define FVHI 34816
#define FVLO 52224
#define FB_SMEM 208896

__global__ __launch_bounds__(256, 1) void flash_attn_mma2(
        const __nv_bfloat16* __restrict__ Qhi, const __nv_bfloat16* __restrict__ Qlo,
        const __nv_bfloat16* __restrict__ Khi, const __nv_bfloat16* __restrict__ Klo,
        const __nv_bfloat16* __restrict__ Vhi, const __nv_bfloat16* __restrict__ Vlo,
        __nv_bfloat16* __restrict__ Ohi, __nv_bfloat16* __restrict__ Olo) {
    extern __shared__ char sm[];
    const uint32_t smem_u32 = smem_to_u32(sm);

    const int qt = blockIdx.x;
    const int h = blockIdx.y;
    const int kvg = h >> 2;
    const int tid = threadIdx.x;
    const int w = tid >> 5;
    const int lane = tid & 31;
    const int lr = lane & 7;
    const int lb8 = (lane >> 3) & 1;
    const int lb16 = (lane >> 4) & 1;
    const int lg = lane >> 2;
    const int tig = lane & 3;
    const int q0 = qt * 128;
    const int qb = w * 16;

    const __nv_bfloat16* kvsrc[4] = {Khi, Klo, Vhi, Vlo};

    auto load_kv = [&](int jt, int buf) {
        const size_t rowbase = (size_t)(jt * 64) * KV_D + kvg * HD;
#pragma unroll
        for (int i = 0; i < 16; i++) {
            int c = tid + i * 256;
            int plane = c >> 10;
            int idx = c & 1023;
            int row = idx >> 4;
            int ch = idx & 15;
            const __nv_bfloat16* src = kvsrc[plane] + rowbase + (size_t)row * KV_D + ch * 8;
            uint32_t dst = smem_u32 + FSTAGE0 + buf * FSTAGE_B + plane * 17408 +
                           (row * QROW + ch * 8) * 2;
            cp_async16(dst, src);
        }
    };

    // Q tile load (both planes), group 0 together with KV0
#pragma unroll
    for (int i = 0; i < 16; i++) {
        int c = tid + i * 256;
        int plane = c >> 11;
        int idx = c & 2047;
        int row = idx >> 4;
        int ch = idx & 15;
        const __nv_bfloat16* src = (plane ? Qlo : Qhi) +
            (size_t)(q0 + row) * D_MODEL + h * HD + ch * 8;
        uint32_t dst = smem_u32 + plane * FOFF_QLO + (row * QROW + ch * 8) * 2;
        cp_async16(dst, src);
    }
    load_kv(0, 0);
    cp_async_commit();
    load_kv(1, 1);
    cp_async_commit();

    // ldmatrix base offsets
    const uint32_t qa_hi = smem_u32 + ((qb + lb8 * 8 + lr) * QROW + lb16 * 8) * 2;
    const uint32_t qa_lo = qa_hi + FOFF_QLO;
    const uint32_t k_off = ((lb16 * 8 + lr) * QROW + lb8 * 8) * 2;        // + ntp*16 rows + kc*32
    const uint32_t v_off = ((lb8 * 8 + lr) * QROW + lb16 * 8) * 2;        // + kc*16 rows + ntp*32

    float m0 = -1e30f, m1 = -1e30f, l0 = 0.0f, l1 = 0.0f;
    float oacc[16][4];
#pragma unroll
    for (int nt = 0; nt < 16; nt++)
#pragma unroll
        for (int j = 0; j < 4; j++) oacc[nt][j] = 0.0f;

    const int njt = 2 * qt + 2;
    for (int jt = 0; jt < njt; jt++) {
        cp_async_wait<1>();
        __syncthreads();

        const bool active = (jt * 64 <= q0 + qb + 15);
        if (active) {
            const uint32_t kvbase = smem_u32 + FSTAGE0 + (jt & 1) * FSTAGE_B;

            // --- S = Q K^T (warp: 16 x 64) ---
            float sacc[8][4];
#pragma unroll
            for (int nt = 0; nt < 8; nt++)
#pragma unroll
                for (int j = 0; j < 4; j++) sacc[nt][j] = 0.0f;

#pragma unroll
            for (int kc = 0; kc < 8; kc++) {
                uint32_t qhi[4], qlo[4];
                ldsm_x4(qhi, qa_hi + kc * 32);
                ldsm_x4(qlo, qa_lo + kc * 32);
#pragma unroll
                for (int ntp = 0; ntp < 4; ntp++) {
                    uint32_t khi[4], klo[4];
                    uint32_t ka = kvbase + k_off + ntp * (16 * QROW * 2) + kc * 32;
                    ldsm_x4(khi, ka);
                    ldsm_x4(klo, ka + FKLO);
                    mma_bf16(sacc[2 * ntp], qhi, khi);
                    mma_bf16(sacc[2 * ntp], qhi, klo);
                    mma_bf16(sacc[2 * ntp], qlo, khi);
                    mma_bf16(sacc[2 * ntp + 1], qhi, khi + 2);
                    mma_bf16(sacc[2 * ntp + 1], qhi, klo + 2);
                    mma_bf16(sacc[2 * ntp + 1], qlo, khi + 2);
                }
            }

            // --- mask ---
            if (jt * 64 + 63 > q0 + qb) {
#pragma unroll
                for (int nt = 0; nt < 8; nt++)
#pragma unroll
                    for (int j = 0; j < 4; j++) {
                        int gj = jt * 64 + nt * 8 + tig * 2 + (j & 1);
                        int gi = q0 + qb + lg + ((j >> 1) << 3);
                        if (gj > gi) sacc[nt][j] = -1e30f;
                    }
            }

            // --- online softmax ---
            float cur0 = -1e30f, cur1 = -1e30f;
#pragma unroll
            for (int nt = 0; nt < 8; nt++) {
                cur0 = fmaxf(cur0, fmaxf(sacc[nt][0], sacc[nt][1]));
                cur1 = fmaxf(cur1, fmaxf(sacc[nt][2], sacc[nt][3]));
            }
            cur0 = fmaxf(cur0, __shfl_xor_sync(0xffffffffu, cur0, 1));
            cur0 = fmaxf(cur0, __shfl_xor_sync(0xffffffffu, cur0, 2));
            cur1 = fmaxf(cur1, __shfl_xor_sync(0xffffffffu, cur1, 1));
            cur1 = fmaxf(cur1, __shfl_xor_sync(0xffffffffu, cur1, 2));

            float mn0 = fmaxf(m0, cur0), mn1 = fmaxf(m1, cur1);
            float alpha0 = __expf(m0 - mn0), alpha1 = __expf(m1 - mn1);
            m0 = mn0; m1 = mn1;

            float rs0 = 0.0f, rs1 = 0.0f;
#pragma unroll
            for (int nt = 0; nt < 8; nt++) {
                sacc[nt][0] = __expf(sacc[nt][0] - mn0);
                sacc[nt][1] = __expf(sacc[nt][1] - mn0);
                sacc[nt][2] = __expf(sacc[nt][2] - mn1);
                sacc[nt][3] = __expf(sacc[nt][3] - mn1);
                rs0 += sacc[nt][0] + sacc[nt][1];
                rs1 += sacc[nt][2] + sacc[nt][3];
            }
            rs0 += __shfl_xor_sync(0xffffffffu, rs0, 1);
            rs0 += __shfl_xor_sync(0xffffffffu, rs0, 2);
            rs1 += __shfl_xor_sync(0xffffffffu, rs1, 1);
            rs1 += __shfl_xor_sync(0xffffffffu, rs1, 2);
            l0 = l0 * alpha0 + rs0;
            l1 = l1 * alpha1 + rs1;

#pragma unroll
            for (int nt = 0; nt < 16; nt++) {
                oacc[nt][0] *= alpha0;
                oacc[nt][1] *= alpha0;
                oacc[nt][2] *= alpha1;
                oacc[nt][3] *= alpha1;
            }

            // --- O += P V ---
#pragma unroll
            for (int kc = 0; kc < 4; kc++) {
                uint32_t ahi[4], alo[4];
                split_bf16(make_float2(sacc[2 * kc][0], sacc[2 * kc][1]), ahi[0], alo[0]);
                split_bf16(make_float2(sacc[2 * kc][2], sacc[2 * kc][3]), ahi[1], alo[1]);
                split_bf16(make_float2(sacc[2 * kc + 1][0], sacc[2 * kc + 1][1]), ahi[2], alo[2]);
                split_bf16(make_float2(sacc[2 * kc + 1][2], sacc[2 * kc + 1][3]), ahi[3], alo[3]);
#pragma unroll
                for (int ntp = 0; ntp < 8; ntp++) {
                    uint32_t vh[4], vl[4];
                    uint32_t va = kvbase + FVHI + v_off + kc * (16 * QROW * 2) + ntp * 32;
                    ldsm_x4t(vh, va);
                    ldsm_x4t(vl, va + (FVLO - FVHI));
                    mma_bf16(oacc[2 * ntp], ahi, vh);
                    mma_bf16(oacc[2 * ntp], alo, vh);
                    mma_bf16(oacc[2 * ntp], ahi, vl);
                    mma_bf16(oacc[2 * ntp + 1], ahi, vh + 2);
                    mma_bf16(oacc[2 * ntp + 1], alo, vh + 2);
                    mma_bf16(oacc[2 * ntp + 1], ahi, vl + 2);
                }
            }
        }

        __syncthreads();
        if (jt + 2 < njt) load_kv(jt + 2, jt & 1);
        cp_async_commit();
    }

    // --- epilogue: write split ctx planes ---
    float inv0 = 1.0f / l0;
    float inv1 = 1.0f / l1;
    int row0 = q0 + qb + lg;
    int row1 = row0 + 8;
#pragma unroll
    for (int nt = 0; nt < 16; nt++) {
        int col = h * HD + nt * 8 + tig * 2;
        uint32_t h0, lo0, h1, lo1;
        split_bf16(make_float2(oacc[nt][0] * inv0, oacc[nt][1] * inv0), h0, lo0);
        split_bf16(make_float2(oacc[nt][2] * inv1, oacc[nt][3] * inv1), h1, lo1);
        *(uint32_t*)&Ohi[(size_t)row0 * D_MODEL + col] = h0;
        *(uint32_t*)&Olo[(size_t)row0 * D_MODEL + col] = lo0;
        *(uint32_t*)&Ohi[(size_t)row1 * D_MODEL + col] = h1;
        *(uint32_t*)&Olo[(size_t)row1 * D_MODEL + col] = lo1;
    }
}

// ---------------------------------------------------------------------------
extern "C" void kernel_launch(void* const* d_in, const int* in_sizes, int n_in,
                              void* d_out, int out_size) {
    const float* x    = (const float*)d_in[0];
    const float* wq   = (const float*)d_in[2];
    const float* wk   = (const float*)d_in[3];
    const float* wv   = (const float*)d_in[4];
    const float* wo   = (const float*)d_in[5];
    const float* cosp = (const float*)d_in[6];
    const float* sinp = (const float*)d_in[7];
    float* out = (float*)d_out;

    float *q, *k, *v;
    cudaGetSymbolAddress((void**)&q, g_q);
    cudaGetSymbolAddress((void**)&k, g_k);
    cudaGetSymbolAddress((void**)&v, g_v);
    __nv_bfloat16 *xhi, *xlo, *qhi, *qlo, *khi, *klo, *vhi, *vlo, *ctxhi, *ctxlo;
    __nv_bfloat16 *wqThi, *wqTlo, *wkThi, *wkTlo, *wvThi, *wvTlo, *woThi, *woTlo;
    cudaGetSymbolAddress((void**)&xhi, g_xhi);
    cudaGetSymbolAddress((void**)&xlo, g_xlo);
    cudaGetSymbolAddress((void**)&qhi, g_qhi);
    cudaGetSymbolAddress((void**)&qlo, g_qlo);
    cudaGetSymbolAddress((void**)&khi, g_khi);
    cudaGetSymbolAddress((void**)&klo, g_klo);
    cudaGetSymbolAddress((void**)&vhi, g_vhi);
    cudaGetSymbolAddress((void**)&vlo, g_vlo);
    cudaGetSymbolAddress((void**)&ctxhi, g_ctxhi);
    cudaGetSymbolAddress((void**)&ctxlo, g_ctxlo);
    cudaGetSymbolAddress((void**)&wqThi, g_wqThi);
    cudaGetSymbolAddress((void**)&wqTlo, g_wqTlo);
    cudaGetSymbolAddress((void**)&wkThi, g_wkThi);
    cudaGetSymbolAddress((void**)&wkTlo, g_wkTlo);
    cudaGetSymbolAddress((void**)&wvThi, g_wvThi);
    cudaGetSymbolAddress((void**)&wvTlo, g_wvTlo);
    cudaGetSymbolAddress((void**)&woThi, g_woThi);
    cudaGetSymbolAddress((void**)&woTlo, g_woTlo);

    cudaFuncSetAttribute(gemm_bf16p, cudaFuncAttributeMaxDynamicSharedMemorySize, GM_SMEM);
    cudaFuncSetAttribute(flash_attn_mma2, cudaFuncAttributeMaxDynamicSharedMemorySize, FB_SMEM);

    // Pre-split x and weights
    {
        int n4 = S_LEN * D_MODEL / 4;
        split_kernel<<<(n4 + 255) / 256, 256>>>(x, xhi, xlo, n4);
    }
    transpose_split_kernel<<<dim3(D_MODEL / 32, D_MODEL / 32), dim3(32, 8)>>>(wq, wqThi, wqTlo, D_MODEL, D_MODEL);
    transpose_split_kernel<<<dim3(KV_D / 32, D_MODEL / 32), dim3(32, 8)>>>(wk, wkThi, wkTlo, D_MODEL, KV_D);
    transpose_split_kernel<<<dim3(KV_D / 32, D_MODEL / 32), dim3(32, 8)>>>(wv, wvThi, wvTlo, D_MODEL, KV_D);
    transpose_split_kernel<<<dim3(D_MODEL / 32, D_MODEL / 32), dim3(32, 8)>>>(wo, woThi, woTlo, D_MODEL, D_MODEL);

    // Projections (fp32 outputs for q/k; v too)
    gemm_bf16p<<<dim3(D_MODEL / 128, S_LEN / 128), 256, GM_SMEM>>>(xhi, xlo, wqThi, wqTlo, q, S_LEN, D_MODEL, D_MODEL);
    gemm_bf16p<<<dim3(KV_D / 128, S_LEN / 128), 256, GM_SMEM>>>(xhi, xlo, wkThi, wkTlo, k, S_LEN, KV_D, D_MODEL);
    gemm_bf16p<<<dim3(KV_D / 128, S_LEN / 128), 256, GM_SMEM>>>(xhi, xlo, wvThi, wvTlo, v, S_LEN, KV_D, D_MODEL);

    // RoPE + scale + split to planes
    {
        int totq = S_LEN * NH * 32;
        rope_split_kernel<<<(totq + 255) / 256, 256>>>(q, cosp, sinp, qhi, qlo, NH, totq, SOFTMAX_SCALE);
        int totk = S_LEN * NG * 32;
        rope_split_kernel<<<(totk + 255) / 256, 256>>>(k, cosp, sinp, khi, klo, NG, totk, 1.0f);
        int n4 = S_LEN * KV_D / 4;
        split_kernel<<<(n4 + 255) / 256, 256>>>(v, vhi, vlo, n4);
    }

    // Flash attention (writes ctx hi/lo planes)
    flash_attn_mma2<<<dim3(S_LEN / 128, NH), 256, FB_SMEM>>>(
        qhi, qlo, khi, klo, vhi, vlo, ctxhi, ctxlo);

    // Output projection
    gemm_bf16p<<<dim3(D_MODEL / 128, S_LEN / 128), 256, GM_SMEM>>>(ctxhi, ctxlo, woThi, woTlo, out, S_LEN, D_MODEL, D_MODEL);
}

// round 8
// speedup vs baseline: 4.2717x; 1.0714x over previous
#include <cuda_runtime.h>
#include <cuda_bf16.h>
#include <cstdint>

// Problem constants
#define S_LEN 4096
#define D_MODEL 2048
#define NH 16
#define NG 4
#define HD 128
#define KV_D (NG * HD)          // 512
#define SOFTMAX_SCALE 0.08838834764831845f  // 1/sqrt(128)

// fp32 scratch (gemm outputs)
__device__ float g_q[S_LEN * D_MODEL];
__device__ float g_k[S_LEN * KV_D];

// bf16 hi/lo planes
__device__ __nv_bfloat16 g_xhi[S_LEN * D_MODEL];
__device__ __nv_bfloat16 g_xlo[S_LEN * D_MODEL];
__device__ __nv_bfloat16 g_qhi[S_LEN * D_MODEL];
__device__ __nv_bfloat16 g_qlo[S_LEN * D_MODEL];
__device__ __nv_bfloat16 g_khi[S_LEN * KV_D];
__device__ __nv_bfloat16 g_klo[S_LEN * KV_D];
__device__ __nv_bfloat16 g_vhi[S_LEN * KV_D];
__device__ __nv_bfloat16 g_vlo[S_LEN * KV_D];
__device__ __nv_bfloat16 g_ctxhi[S_LEN * D_MODEL];
__device__ __nv_bfloat16 g_ctxlo[S_LEN * D_MODEL];
__device__ __nv_bfloat16 g_wqThi[D_MODEL * D_MODEL];
__device__ __nv_bfloat16 g_wqTlo[D_MODEL * D_MODEL];
__device__ __nv_bfloat16 g_wkThi[KV_D * D_MODEL];
__device__ __nv_bfloat16 g_wkTlo[KV_D * D_MODEL];
__device__ __nv_bfloat16 g_wvThi[KV_D * D_MODEL];
__device__ __nv_bfloat16 g_wvTlo[KV_D * D_MODEL];
__device__ __nv_bfloat16 g_woThi[D_MODEL * D_MODEL];
__device__ __nv_bfloat16 g_woTlo[D_MODEL * D_MODEL];

// ---------------------------------------------------------------------------
// Helpers
// ---------------------------------------------------------------------------
__device__ __forceinline__ uint32_t smem_to_u32(const void* p) {
    uint32_t a;
    asm("{ .reg .u64 t; cvta.to.shared.u64 t, %1; cvt.u32.u64 %0, t; }"
        : "=r"(a) : "l"(p));
    return a;
}

__device__ __forceinline__ void cp_async16(uint32_t smem_addr, const void* gptr) {
    asm volatile("cp.async.cg.shared.global [%0], [%1], 16;" :: "r"(smem_addr), "l"(gptr));
}
__device__ __forceinline__ void cp_async_commit() {
    asm volatile("cp.async.commit_group;" ::: "memory");
}
template <int N>
__device__ __forceinline__ void cp_async_wait() {
    asm volatile("cp.async.wait_group %0;" :: "n"(N) : "memory");
}

__device__ __forceinline__ uint32_t pack_bf16(float x, float y) {
    uint32_t r;
    asm("cvt.rn.bf16x2.f32 %0, %1, %2;" : "=r"(r) : "f"(y), "f"(x));
    return r;
}
__device__ __forceinline__ float bf16lo_f32(uint32_t h) { return __uint_as_float(h << 16); }
__device__ __forceinline__ float bf16hi_f32(uint32_t h) { return __uint_as_float(h & 0xffff0000u); }

__device__ __forceinline__ void split_bf16(float2 f, uint32_t& hi, uint32_t& lo) {
    hi = pack_bf16(f.x, f.y);
    float rx = f.x - bf16lo_f32(hi);
    float ry = f.y - bf16hi_f32(hi);
    lo = pack_bf16(rx, ry);
}

__device__ __forceinline__ void mma_bf16(float* c, const uint32_t* a, const uint32_t* b) {
    asm volatile(
        "mma.sync.aligned.m16n8k16.row.col.f32.bf16.bf16.f32 "
        "{%0,%1,%2,%3}, {%4,%5,%6,%7}, {%8,%9}, {%0,%1,%2,%3};"
        : "+f"(c[0]), "+f"(c[1]), "+f"(c[2]), "+f"(c[3])
        : "r"(a[0]), "r"(a[1]), "r"(a[2]), "r"(a[3]), "r"(b[0]), "r"(b[1]));
}

__device__ __forceinline__ void ldsm_x4(uint32_t* r, uint32_t addr) {
    asm volatile("ldmatrix.sync.aligned.m8n8.x4.shared.b16 {%0,%1,%2,%3}, [%4];"
        : "=r"(r[0]), "=r"(r[1]), "=r"(r[2]), "=r"(r[3]) : "r"(addr));
}
__device__ __forceinline__ void ldsm_x4t(uint32_t* r, uint32_t addr) {
    asm volatile("ldmatrix.sync.aligned.m8n8.x4.trans.shared.b16 {%0,%1,%2,%3}, [%4];"
        : "=r"(r[0]), "=r"(r[1]), "=r"(r[2]), "=r"(r[3]) : "r"(addr));
}

// ---------------------------------------------------------------------------
// Split kernels
// ---------------------------------------------------------------------------
__global__ void split_kernel(const float* __restrict__ in,
                             __nv_bfloat16* __restrict__ hi,
                             __nv_bfloat16* __restrict__ lo,
                             int n4) {
    int idx = blockIdx.x * blockDim.x + threadIdx.x;
    if (idx >= n4) return;
    float4 v = ((const float4*)in)[idx];
    uint32_t h01, l01, h23, l23;
    split_bf16(make_float2(v.x, v.y), h01, l01);
    split_bf16(make_float2(v.z, v.w), h23, l23);
    ((uint2*)hi)[idx] = make_uint2(h01, h23);
    ((uint2*)lo)[idx] = make_uint2(l01, l23);
}

// rope + scale + split
__global__ void rope_split_kernel(const float* __restrict__ t,
                                  const float* __restrict__ cosp,
                                  const float* __restrict__ sinp,
                                  __nv_bfloat16* __restrict__ hi,
                                  __nv_bfloat16* __restrict__ lo,
                                  int nh, int total, float scale) {
    int idx = blockIdx.x * blockDim.x + threadIdx.x;
    if (idx >= total) return;
    int i = idx & 31;
    int h = (idx >> 5) % nh;
    int s = idx / (32 * nh);
    int d0 = 2 * i;
    const float* row = t + (size_t)s * (nh * 128) + h * 128;
    float a0 = row[d0], a1 = row[d0 + 1];
    float b0 = row[d0 + 64], b1 = row[d0 + 65];
    float c0 = cosp[s * 128 + d0], c1 = cosp[s * 128 + d0 + 1];
    float s0 = sinp[s * 128 + d0], s1 = sinp[s * 128 + d0 + 1];
    float c2 = cosp[s * 128 + d0 + 64], c3 = cosp[s * 128 + d0 + 65];
    float s2 = sinp[s * 128 + d0 + 64], s3 = sinp[s * 128 + d0 + 65];
    float o0 = (a0 * c0 - b0 * s0) * scale;
    float o1 = (a1 * c1 - b1 * s1) * scale;
    float o2 = (b0 * c2 + a0 * s2) * scale;
    float o3 = (b1 * c3 + a1 * s3) * scale;
    uint32_t h01, l01, h23, l23;
    split_bf16(make_float2(o0, o1), h01, l01);
    split_bf16(make_float2(o2, o3), h23, l23);
    size_t base = (size_t)s * (nh * 128) + h * 128;
    *(uint32_t*)&hi[base + d0] = h01;
    *(uint32_t*)&lo[base + d0] = l01;
    *(uint32_t*)&hi[base + d0 + 64] = h23;
    *(uint32_t*)&lo[base + d0 + 64] = l23;
}

// transpose + split
__global__ void transpose_split_kernel(const float* __restrict__ in,
                                       __nv_bfloat16* __restrict__ hiT,
                                       __nv_bfloat16* __restrict__ loT,
                                       int R, int C) {
    __shared__ float t[32][33];
    int c0 = blockIdx.x * 32, r0 = blockIdx.y * 32;
    int x = threadIdx.x, y = threadIdx.y;
#pragma unroll
    for (int i = y; i < 32; i += 8) t[i][x] = in[(size_t)(r0 + i) * C + c0 + x];
    __syncthreads();
#pragma unroll
    for (int i = y; i < 32; i += 8) {
        float v = t[x][i];
        __nv_bfloat16 h = __float2bfloat16(v);
        __nv_bfloat16 l = __float2bfloat16(v - __bfloat162float(h));
        size_t o = (size_t)(c0 + i) * R + r0 + x;
        hiT[o] = h;
        loT[o] = l;
    }
}

// ---------------------------------------------------------------------------
// GEMM 128x128 (for K/V projections). Optional split epilogue (Chi/Clo).
// ---------------------------------------------------------------------------
#define SROWB 56
#define PLANE_B (128 * SROWB * 2)
#define GSTAGE_B (4 * PLANE_B)
#define GM_NST 3
#define GM_SMEM (GM_NST * GSTAGE_B)

__global__ __launch_bounds__(256, 1) void gemm_bf16p(
        const __nv_bfloat16* __restrict__ Ahi, const __nv_bfloat16* __restrict__ Alo,
        const __nv_bfloat16* __restrict__ Bhi, const __nv_bfloat16* __restrict__ Blo,
        float* __restrict__ C,
        __nv_bfloat16* __restrict__ Chi, __nv_bfloat16* __restrict__ Clo,
        int M, int N, int K) {
    extern __shared__ char sm[];
    const uint32_t smem_u32 = smem_to_u32(sm);

    const int tid = threadIdx.x;
    const int wid = tid >> 5;
    const int lane = tid & 31;
    const int lr = lane & 7;
    const int lb8 = (lane >> 3) & 1;
    const int lb16 = (lane >> 4) & 1;
    const int wm = wid >> 2;
    const int wn = wid & 3;
    const int m0 = blockIdx.y * 128;
    const int n0 = blockIdx.x * 128;
    const int NS = K >> 5;

    const __nv_bfloat16* srcs[4] = {Ahi, Alo, Bhi, Blo};

    auto load_stage = [&](int s, int buf) {
        const int k0 = s << 5;
#pragma unroll
        for (int i = 0; i < 8; i++) {
            int c = tid + i * 256;
            int plane = c >> 9;
            int idx = c & 511;
            int row = idx >> 2;
            int ch = idx & 3;
            int grow = (plane < 2 ? m0 : n0) + row;
            const __nv_bfloat16* g = srcs[plane] + (size_t)grow * K + k0 + ch * 8;
            uint32_t dst = smem_u32 + buf * GSTAGE_B + plane * PLANE_B +
                           (row * SROWB + ch * 8) * 2;
            cp_async16(dst, g);
        }
    };

    float acc[4][4][4];
#pragma unroll
    for (int m = 0; m < 4; m++)
#pragma unroll
        for (int n = 0; n < 4; n++)
#pragma unroll
            for (int i = 0; i < 4; i++) acc[m][n][i] = 0.0f;

    load_stage(0, 0); cp_async_commit();
    load_stage(1, 1); cp_async_commit();
    load_stage(2, 2); cp_async_commit();

    const uint32_t a_off = ((wm * 64 + lr + lb8 * 8) * SROWB + lb16 * 8) * 2;
    const uint32_t b_off = 2 * PLANE_B + ((wn * 32 + lr + lb16 * 8) * SROWB + lb8 * 8) * 2;

    for (int s = 0; s < NS; s++) {
        const int buf = s % GM_NST;
        cp_async_wait<GM_NST - 1>();
        __syncthreads();

        const uint32_t base = smem_u32 + buf * GSTAGE_B;

#pragma unroll
        for (int ks = 0; ks < 32; ks += 16) {
            uint32_t bhi[2][4], blo[2][4];
#pragma unroll
            for (int np = 0; np < 2; np++) {
                uint32_t addr = base + b_off + (np * 16 * SROWB + ks) * 2;
                ldsm_x4(bhi[np], addr);
                ldsm_x4(blo[np], addr + PLANE_B);
            }
#pragma unroll
            for (int m = 0; m < 4; m++) {
                uint32_t ahi[4], alo[4];
                uint32_t addr = base + a_off + (m * 16 * SROWB + ks) * 2;
                ldsm_x4(ahi, addr);
                ldsm_x4(alo, addr + PLANE_B);
#pragma unroll
                for (int n = 0; n < 4; n++) {
                    const uint32_t* bh = &bhi[n >> 1][(n & 1) * 2];
                    const uint32_t* bl = &blo[n >> 1][(n & 1) * 2];
                    mma_bf16(acc[m][n], ahi, bh);
                    mma_bf16(acc[m][n], ahi, bl);
                    mma_bf16(acc[m][n], alo, bh);
                }
            }
        }

        __syncthreads();
        if (s + GM_NST < NS) load_stage(s + GM_NST, buf);
        cp_async_commit();
    }

    const int g = lane >> 2;
    const int tig = lane & 3;
#pragma unroll
    for (int m = 0; m < 4; m++) {
        int r0 = m0 + wm * 64 + m * 16 + g;
        int r1 = r0 + 8;
#pragma unroll
        for (int n = 0; n < 4; n++) {
            int col = n0 + wn * 32 + n * 8 + tig * 2;
            if (Chi) {
                uint32_t h0, lo0, h1, lo1;
                split_bf16(make_float2(acc[m][n][0], acc[m][n][1]), h0, lo0);
                split_bf16(make_float2(acc[m][n][2], acc[m][n][3]), h1, lo1);
                *(uint32_t*)&Chi[(size_t)r0 * N + col] = h0;
                *(uint32_t*)&Clo[(size_t)r0 * N + col] = lo0;
                *(uint32_t*)&Chi[(size_t)r1 * N + col] = h1;
                *(uint32_t*)&Clo[(size_t)r1 * N + col] = lo1;
            } else {
                *(float2*)(C + (size_t)r0 * N + col) = make_float2(acc[m][n][0], acc[m][n][1]);
                *(float2*)(C + (size_t)r1 * N + col) = make_float2(acc[m][n][2], acc[m][n][3]);
            }
        }
    }
}

// ---------------------------------------------------------------------------
// GEMM 128x256 wide (for Q/O projections). Warp tile 64x64, 2-stage cp.async.
// Stage layout: AHI@0 (14336), ALO@14336, BHI@28672 (28672), BLO@57344.
// ---------------------------------------------------------------------------
#define WA_PL 14336
#define WB_PL 28672
#define WSTAGE_B 86016
#define GW_SMEM (2 * WSTAGE_B)   // 172032

__global__ __launch_bounds__(256, 1) void gemm_bf16p_wide(
        const __nv_bfloat16* __restrict__ Ahi, const __nv_bfloat16* __restrict__ Alo,
        const __nv_bfloat16* __restrict__ Bhi, const __nv_bfloat16* __restrict__ Blo,
        float* __restrict__ C, int M, int N, int K) {
    extern __shared__ char sm[];
    const uint32_t smem_u32 = smem_to_u32(sm);

    const int tid = threadIdx.x;
    const int wid = tid >> 5;
    const int lane = tid & 31;
    const int lr = lane & 7;
    const int lb8 = (lane >> 3) & 1;
    const int lb16 = (lane >> 4) & 1;
    const int wm = wid >> 2;       // 0..1 (64 rows)
    const int wn = wid & 3;        // 0..3 (64 cols)
    const int m0 = blockIdx.y * 128;
    const int n0 = blockIdx.x * 256;
    const int NS = K >> 5;

    auto load_stage = [&](int s, int buf) {
        const int k0 = s << 5;
        const uint32_t base = smem_u32 + buf * WSTAGE_B;
#pragma unroll
        for (int i = 0; i < 12; i++) {
            int c = tid + i * 256;   // 0..3071
            if (c < 1024) {
                int pl = c >> 9;
                int idx = c & 511;
                int row = idx >> 2;
                int ch = idx & 3;
                const __nv_bfloat16* g = (pl ? Alo : Ahi) + (size_t)(m0 + row) * K + k0 + ch * 8;
                cp_async16(base + pl * WA_PL + (row * SROWB + ch * 8) * 2, g);
            } else {
                int cb = c - 1024;
                int pl = cb >> 10;
                int idx = cb & 1023;
                int row = idx >> 2;
                int ch = idx & 3;
                const __nv_bfloat16* g = (pl ? Blo : Bhi) + (size_t)(n0 + row) * K + k0 + ch * 8;
                cp_async16(base + 2 * WA_PL + pl * WB_PL + (row * SROWB + ch * 8) * 2, g);
            }
        }
    };

    float acc[4][8][4];
#pragma unroll
    for (int m = 0; m < 4; m++)
#pragma unroll
        for (int n = 0; n < 8; n++)
#pragma unroll
            for (int i = 0; i < 4; i++) acc[m][n][i] = 0.0f;

    load_stage(0, 0); cp_async_commit();
    load_stage(1, 1); cp_async_commit();

    const uint32_t a_off = ((wm * 64 + lr + lb8 * 8) * SROWB + lb16 * 8) * 2;
    const uint32_t b_off = 2 * WA_PL + ((wn * 64 + lr + lb16 * 8) * SROWB + lb8 * 8) * 2;

    for (int s = 0; s < NS; s++) {
        const int buf = s & 1;
        cp_async_wait<1>();
        __syncthreads();

        const uint32_t base = smem_u32 + buf * WSTAGE_B;

#pragma unroll
        for (int ks = 0; ks < 32; ks += 16) {
            uint32_t bhi[4][4], blo[4][4];
#pragma unroll
            for (int np = 0; np < 4; np++) {
                uint32_t addr = base + b_off + (np * 16 * SROWB + ks) * 2;
                ldsm_x4(bhi[np], addr);
                ldsm_x4(blo[np], addr + WB_PL);
            }
#pragma unroll
            for (int m = 0; m < 4; m++) {
                uint32_t ahi[4], alo[4];
                uint32_t addr = base + a_off + (m * 16 * SROWB + ks) * 2;
                ldsm_x4(ahi, addr);
                ldsm_x4(alo, addr + WA_PL);
#pragma unroll
                for (int n = 0; n < 8; n++) {
                    const uint32_t* bh = &bhi[n >> 1][(n & 1) * 2];
                    const uint32_t* bl = &blo[n >> 1][(n & 1) * 2];
                    mma_bf16(acc[m][n], ahi, bh);
                    mma_bf16(acc[m][n], ahi, bl);
                    mma_bf16(acc[m][n], alo, bh);
                }
            }
        }

        __syncthreads();
        if (s + 2 < NS) load_stage(s + 2, buf);
        cp_async_commit();
    }

    const int g = lane >> 2;
    const int tig = lane & 3;
#pragma unroll
    for (int m = 0; m < 4; m++) {
        int r0 = m0 + wm * 64 + m * 16 + g;
        int r1 = r0 + 8;
#pragma unroll
        for (int n = 0; n < 8; n++) {
            int col = n0 + wn * 64 + n * 8 + tig * 2;
            *(float2*)(C + (size_t)r0 * N + col) = make_float2(acc[m][n][0], acc[m][n][1]);
            *(float2*)(C + (size_t)r1 * N + col) = make_float2(acc[m][n][2], acc[m][n][3]);
        }
    }
}

// ---------------------------------------------------------------------------
// Flash attention v2 (round-7) + reversed block order for load balance.
// ---------------------------------------------------------------------------
#define QROW 136
#define FOFF_QLO 34816
#define FSTAGE0 69632
#define FSTAGE_B 69632
#define FKLO 17408
#define FVHI 34816
#define FVLO 52224
#define FB_SMEM 208896

__global__ __launch_bounds__(256, 1) void flash_attn_mma2(
        const __nv_bfloat16* __restrict__ Qhi, const __nv_bfloat16* __restrict__ Qlo,
        const __nv_bfloat16* __restrict__ Khi, const __nv_bfloat16* __restrict__ Klo,
        const __nv_bfloat16* __restrict__ Vhi, const __nv_bfloat16* __restrict__ Vlo,
        __nv_bfloat16* __restrict__ Ohi, __nv_bfloat16* __restrict__ Olo) {
    extern __shared__ char sm[];
    const uint32_t smem_u32 = smem_to_u32(sm);

    const int qt = (int)gridDim.x - 1 - (int)blockIdx.x;   // heavy tiles first
    const int h = blockIdx.y;
    const int kvg = h >> 2;
    const int tid = threadIdx.x;
    const int w = tid >> 5;
    const int lane = tid & 31;
    const int lr = lane & 7;
    const int lb8 = (lane >> 3) & 1;
    const int lb16 = (lane >> 4) & 1;
    const int lg = lane >> 2;
    const int tig = lane & 3;
    const int q0 = qt * 128;
    const int qb = w * 16;

    const __nv_bfloat16* kvsrc[4] = {Khi, Klo, Vhi, Vlo};

    auto load_kv = [&](int jt, int buf) {
        const size_t rowbase = (size_t)(jt * 64) * KV_D + kvg * HD;
#pragma unroll
        for (int i = 0; i < 16; i++) {
            int c = tid + i * 256;
            int plane = c >> 10;
            int idx = c & 1023;
            int row = idx >> 4;
            int ch = idx & 15;
            const __nv_bfloat16* src = kvsrc[plane] + rowbase + (size_t)row * KV_D + ch * 8;
            uint32_t dst = smem_u32 + FSTAGE0 + buf * FSTAGE_B + plane * 17408 +
                           (row * QROW + ch * 8) * 2;
            cp_async16(dst, src);
        }
    };

#pragma unroll
    for (int i = 0; i < 16; i++) {
        int c = tid + i * 256;
        int plane = c >> 11;
        int idx = c & 2047;
        int row = idx >> 4;
        int ch = idx & 15;
        const __nv_bfloat16* src = (plane ? Qlo : Qhi) +
            (size_t)(q0 + row) * D_MODEL + h * HD + ch * 8;
        uint32_t dst = smem_u32 + plane * FOFF_QLO + (row * QROW + ch * 8) * 2;
        cp_async16(dst, src);
    }
    load_kv(0, 0);
    cp_async_commit();
    load_kv(1, 1);
    cp_async_commit();

    const uint32_t qa_hi = smem_u32 + ((qb + lb8 * 8 + lr) * QROW + lb16 * 8) * 2;
    const uint32_t qa_lo = qa_hi + FOFF_QLO;
    const uint32_t k_off = ((lb16 * 8 + lr) * QROW + lb8 * 8) * 2;
    const uint32_t v_off = ((lb8 * 8 + lr) * QROW + lb16 * 8) * 2;

    float m0 = -1e30f, m1 = -1e30f, l0 = 0.0f, l1 = 0.0f;
    float oacc[16][4];
#pragma unroll
    for (int nt = 0; nt < 16; nt++)
#pragma unroll
        for (int j = 0; j < 4; j++) oacc[nt][j] = 0.0f;

    const int njt = 2 * qt + 2;
    for (int jt = 0; jt < njt; jt++) {
        cp_async_wait<1>();
        __syncthreads();

        const bool active = (jt * 64 <= q0 + qb + 15);
        if (active) {
            const uint32_t kvbase = smem_u32 + FSTAGE0 + (jt & 1) * FSTAGE_B;

            float sacc[8][4];
#pragma unroll
            for (int nt = 0; nt < 8; nt++)
#pragma unroll
                for (int j = 0; j < 4; j++) sacc[nt][j] = 0.0f;

#pragma unroll
            for (int kc = 0; kc < 8; kc++) {
                uint32_t qhi[4], qlo[4];
                ldsm_x4(qhi, qa_hi + kc * 32);
                ldsm_x4(qlo, qa_lo + kc * 32);
#pragma unroll
                for (int ntp = 0; ntp < 4; ntp++) {
                    uint32_t khi[4], klo[4];
                    uint32_t ka = kvbase + k_off + ntp * (16 * QROW * 2) + kc * 32;
                    ldsm_x4(khi, ka);
                    ldsm_x4(klo, ka + FKLO);
                    mma_bf16(sacc[2 * ntp], qhi, khi);
                    mma_bf16(sacc[2 * ntp], qhi, klo);
                    mma_bf16(sacc[2 * ntp], qlo, khi);
                    mma_bf16(sacc[2 * ntp + 1], qhi, khi + 2);
                    mma_bf16(sacc[2 * ntp + 1], qhi, klo + 2);
                    mma_bf16(sacc[2 * ntp + 1], qlo, khi + 2);
                }
            }

            if (jt * 64 + 63 > q0 + qb) {
#pragma unroll
                for (int nt = 0; nt < 8; nt++)
#pragma unroll
                    for (int j = 0; j < 4; j++) {
                        int gj = jt * 64 + nt * 8 + tig * 2 + (j & 1);
                        int gi = q0 + qb + lg + ((j >> 1) << 3);
                        if (gj > gi) sacc[nt][j] = -1e30f;
                    }
            }

            float cur0 = -1e30f, cur1 = -1e30f;
#pragma unroll
            for (int nt = 0; nt < 8; nt++) {
                cur0 = fmaxf(cur0, fmaxf(sacc[nt][0], sacc[nt][1]));
                cur1 = fmaxf(cur1, fmaxf(sacc[nt][2], sacc[nt][3]));
            }
            cur0 = fmaxf(cur0, __shfl_xor_sync(0xffffffffu, cur0, 1));
            cur0 = fmaxf(cur0, __shfl_xor_sync(0xffffffffu, cur0, 2));
            cur1 = fmaxf(cur1, __shfl_xor_sync(0xffffffffu, cur1, 1));
            cur1 = fmaxf(cur1, __shfl_xor_sync(0xffffffffu, cur1, 2));

            float mn0 = fmaxf(m0, cur0), mn1 = fmaxf(m1, cur1);
            float alpha0 = __expf(m0 - mn0), alpha1 = __expf(m1 - mn1);
            m0 = mn0; m1 = mn1;

            float rs0 = 0.0f, rs1 = 0.0f;
#pragma unroll
            for (int nt = 0; nt < 8; nt++) {
                sacc[nt][0] = __expf(sacc[nt][0] - mn0);
                sacc[nt][1] = __expf(sacc[nt][1] - mn0);
                sacc[nt][2] = __expf(sacc[nt][2] - mn1);
                sacc[nt][3] = __expf(sacc[nt][3] - mn1);
                rs0 += sacc[nt][0] + sacc[nt][1];
                rs1 += sacc[nt][2] + sacc[nt][3];
            }
            rs0 += __shfl_xor_sync(0xffffffffu, rs0, 1);
            rs0 += __shfl_xor_sync(0xffffffffu, rs0, 2);
            rs1 += __shfl_xor_sync(0xffffffffu, rs1, 1);
            rs1 += __shfl_xor_sync(0xffffffffu, rs1, 2);
            l0 = l0 * alpha0 + rs0;
            l1 = l1 * alpha1 + rs1;

#pragma unroll
            for (int nt = 0; nt < 16; nt++) {
                oacc[nt][0] *= alpha0;
                oacc[nt][1] *= alpha0;
                oacc[nt][2] *= alpha1;
                oacc[nt][3] *= alpha1;
            }

#pragma unroll
            for (int kc = 0; kc < 4; kc++) {
                uint32_t ahi[4], alo[4];
                split_bf16(make_float2(sacc[2 * kc][0], sacc[2 * kc][1]), ahi[0], alo[0]);
                split_bf16(make_float2(sacc[2 * kc][2], sacc[2 * kc][3]), ahi[1], alo[1]);
                split_bf16(make_float2(sacc[2 * kc + 1][0], sacc[2 * kc + 1][1]), ahi[2], alo[2]);
                split_bf16(make_float2(sacc[2 * kc + 1][2], sacc[2 * kc + 1][3]), ahi[3], alo[3]);
#pragma unroll
                for (int ntp = 0; ntp < 8; ntp++) {
                    uint32_t vh[4], vl[4];
                    uint32_t va = kvbase + FVHI + v_off + kc * (16 * QROW * 2) + ntp * 32;
                    ldsm_x4t(vh, va);
                    ldsm_x4t(vl, va + (FVLO - FVHI));
                    mma_bf16(oacc[2 * ntp], ahi, vh);
                    mma_bf16(oacc[2 * ntp], alo, vh);
                    mma_bf16(oacc[2 * ntp], ahi, vl);
                    mma_bf16(oacc[2 * ntp + 1], ahi, vh + 2);
                    mma_bf16(oacc[2 * ntp + 1], alo, vh + 2);
                    mma_bf16(oacc[2 * ntp + 1], ahi, vl + 2);
                }
            }
        }

        __syncthreads();
        if (jt + 2 < njt) load_kv(jt + 2, jt & 1);
        cp_async_commit();
    }

    float inv0 = 1.0f / l0;
    float inv1 = 1.0f / l1;
    int row0 = q0 + qb + lg;
    int row1 = row0 + 8;
#pragma unroll
    for (int nt = 0; nt < 16; nt++) {
        int col = h * HD + nt * 8 + tig * 2;
        uint32_t h0, lo0, h1, lo1;
        split_bf16(make_float2(oacc[nt][0] * inv0, oacc[nt][1] * inv0), h0, lo0);
        split_bf16(make_float2(oacc[nt][2] * inv1, oacc[nt][3] * inv1), h1, lo1);
        *(uint32_t*)&Ohi[(size_t)row0 * D_MODEL + col] = h0;
        *(uint32_t*)&Olo[(size_t)row0 * D_MODEL + col] = lo0;
        *(uint32_t*)&Ohi[(size_t)row1 * D_MODEL + col] = h1;
        *(uint32_t*)&Olo[(size_t)row1 * D_MODEL + col] = lo1;
    }
}

// ---------------------------------------------------------------------------
extern "C" void kernel_launch(void* const* d_in, const int* in_sizes, int n_in,
                              void* d_out, int out_size) {
    const float* x    = (const float*)d_in[0];
    const float* wq   = (const float*)d_in[2];
    const float* wk   = (const float*)d_in[3];
    const float* wv   = (const float*)d_in[4];
    const float* wo   = (const float*)d_in[5];
    const float* cosp = (const float*)d_in[6];
    const float* sinp = (const float*)d_in[7];
    float* out = (float*)d_out;

    float *q, *k;
    cudaGetSymbolAddress((void**)&q, g_q);
    cudaGetSymbolAddress((void**)&k, g_k);
    __nv_bfloat16 *xhi, *xlo, *qhi, *qlo, *khi, *klo, *vhi, *vlo, *ctxhi, *ctxlo;
    __nv_bfloat16 *wqThi, *wqTlo, *wkThi, *wkTlo, *wvThi, *wvTlo, *woThi, *woTlo;
    cudaGetSymbolAddress((void**)&xhi, g_xhi);
    cudaGetSymbolAddress((void**)&xlo, g_xlo);
    cudaGetSymbolAddress((void**)&qhi, g_qhi);
    cudaGetSymbolAddress((void**)&qlo, g_qlo);
    cudaGetSymbolAddress((void**)&khi, g_khi);
    cudaGetSymbolAddress((void**)&klo, g_klo);
    cudaGetSymbolAddress((void**)&vhi, g_vhi);
    cudaGetSymbolAddress((void**)&vlo, g_vlo);
    cudaGetSymbolAddress((void**)&ctxhi, g_ctxhi);
    cudaGetSymbolAddress((void**)&ctxlo, g_ctxlo);
    cudaGetSymbolAddress((void**)&wqThi, g_wqThi);
    cudaGetSymbolAddress((void**)&wqTlo, g_wqTlo);
    cudaGetSymbolAddress((void**)&wkThi, g_wkThi);
    cudaGetSymbolAddress((void**)&wkTlo, g_wkTlo);
    cudaGetSymbolAddress((void**)&wvThi, g_wvThi);
    cudaGetSymbolAddress((void**)&wvTlo, g_wvTlo);
    cudaGetSymbolAddress((void**)&woThi, g_woThi);
    cudaGetSymbolAddress((void**)&woTlo, g_woTlo);

    cudaFuncSetAttribute(gemm_bf16p, cudaFuncAttributeMaxDynamicSharedMemorySize, GM_SMEM);
    cudaFuncSetAttribute(gemm_bf16p_wide, cudaFuncAttributeMaxDynamicSharedMemorySize, GW_SMEM);
    cudaFuncSetAttribute(flash_attn_mma2, cudaFuncAttributeMaxDynamicSharedMemorySize, FB_SMEM);

    // Pre-split x and weights
    {
        int n4 = S_LEN * D_MODEL / 4;
        split_kernel<<<(n4 + 255) / 256, 256>>>(x, xhi, xlo, n4);
    }
    transpose_split_kernel<<<dim3(D_MODEL / 32, D_MODEL / 32), dim3(32, 8)>>>(wq, wqThi, wqTlo, D_MODEL, D_MODEL);
    transpose_split_kernel<<<dim3(KV_D / 32, D_MODEL / 32), dim3(32, 8)>>>(wk, wkThi, wkTlo, D_MODEL, KV_D);
    transpose_split_kernel<<<dim3(KV_D / 32, D_MODEL / 32), dim3(32, 8)>>>(wv, wvThi, wvTlo, D_MODEL, KV_D);
    transpose_split_kernel<<<dim3(D_MODEL / 32, D_MODEL / 32), dim3(32, 8)>>>(wo, woThi, woTlo, D_MODEL, D_MODEL);

    // Projections
    gemm_bf16p_wide<<<dim3(D_MODEL / 256, S_LEN / 128), 256, GW_SMEM>>>(
        xhi, xlo, wqThi, wqTlo, q, S_LEN, D_MODEL, D_MODEL);
    gemm_bf16p<<<dim3(KV_D / 128, S_LEN / 128), 256, GM_SMEM>>>(
        xhi, xlo, wkThi, wkTlo, k, nullptr, nullptr, S_LEN, KV_D, D_MODEL);
    gemm_bf16p<<<dim3(KV_D / 128, S_LEN / 128), 256, GM_SMEM>>>(
        xhi, xlo, wvThi, wvTlo, nullptr, vhi, vlo, S_LEN, KV_D, D_MODEL);

    // RoPE + scale + split to planes
    {
        int totq = S_LEN * NH * 32;
        rope_split_kernel<<<(totq + 255) / 256, 256>>>(q, cosp, sinp, qhi, qlo, NH, totq, SOFTMAX_SCALE);
        int totk = S_LEN * NG * 32;
        rope_split_kernel<<<(totk + 255) / 256, 256>>>(k, cosp, sinp, khi, klo, NG, totk, 1.0f);
    }

    // Flash attention (writes ctx hi/lo planes)
    flash_attn_mma2<<<dim3(S_LEN / 128, NH), 256, FB_SMEM>>>(
        qhi, qlo, khi, klo, vhi, vlo, ctxhi, ctxlo);

    // Output projection
    gemm_bf16p_wide<<<dim3(D_MODEL / 256, S_LEN / 128), 256, GW_SMEM>>>(
        ctxhi, ctxlo, woThi, woTlo, out, S_LEN, D_MODEL, D_MODEL);
}

// round 9
// speedup vs baseline: 4.6545x; 1.0896x over previous
#include <cuda_runtime.h>
#include <cuda_bf16.h>
#include <cstdint>

// Problem constants
#define S_LEN 4096
#define D_MODEL 2048
#define NH 16
#define NG 4
#define HD 128
#define KV_D (NG * HD)          // 512
#define SOFTMAX_SCALE 0.08838834764831845f  // 1/sqrt(128)

// bf16 hi/lo planes
__device__ __nv_bfloat16 g_xhi[S_LEN * D_MODEL];
__device__ __nv_bfloat16 g_xlo[S_LEN * D_MODEL];
__device__ __nv_bfloat16 g_qhi[S_LEN * D_MODEL];
__device__ __nv_bfloat16 g_qlo[S_LEN * D_MODEL];
__device__ __nv_bfloat16 g_khi[S_LEN * KV_D];
__device__ __nv_bfloat16 g_klo[S_LEN * KV_D];
__device__ __nv_bfloat16 g_vhi[S_LEN * KV_D];
__device__ __nv_bfloat16 g_vlo[S_LEN * KV_D];
__device__ __nv_bfloat16 g_ctxhi[S_LEN * D_MODEL];
__device__ __nv_bfloat16 g_ctxlo[S_LEN * D_MODEL];
__device__ __nv_bfloat16 g_wqThi[D_MODEL * D_MODEL];
__device__ __nv_bfloat16 g_wqTlo[D_MODEL * D_MODEL];
__device__ __nv_bfloat16 g_wkvThi[2 * KV_D * D_MODEL];  // rows 0-511 K, 512-1023 V
__device__ __nv_bfloat16 g_wkvTlo[2 * KV_D * D_MODEL];
__device__ __nv_bfloat16 g_woThi[D_MODEL * D_MODEL];
__device__ __nv_bfloat16 g_woTlo[D_MODEL * D_MODEL];

// ---------------------------------------------------------------------------
// Helpers
// ---------------------------------------------------------------------------
__device__ __forceinline__ uint32_t smem_to_u32(const void* p) {
    uint32_t a;
    asm("{ .reg .u64 t; cvta.to.shared.u64 t, %1; cvt.u32.u64 %0, t; }"
        : "=r"(a) : "l"(p));
    return a;
}

__device__ __forceinline__ void cp_async16(uint32_t smem_addr, const void* gptr) {
    asm volatile("cp.async.cg.shared.global [%0], [%1], 16;" :: "r"(smem_addr), "l"(gptr));
}
__device__ __forceinline__ void cp_async_commit() {
    asm volatile("cp.async.commit_group;" ::: "memory");
}
template <int N>
__device__ __forceinline__ void cp_async_wait() {
    asm volatile("cp.async.wait_group %0;" :: "n"(N) : "memory");
}

__device__ __forceinline__ uint32_t pack_bf16(float x, float y) {
    uint32_t r;
    asm("cvt.rn.bf16x2.f32 %0, %1, %2;" : "=r"(r) : "f"(y), "f"(x));
    return r;
}
__device__ __forceinline__ float bf16lo_f32(uint32_t h) { return __uint_as_float(h << 16); }
__device__ __forceinline__ float bf16hi_f32(uint32_t h) { return __uint_as_float(h & 0xffff0000u); }

__device__ __forceinline__ void split_bf16(float2 f, uint32_t& hi, uint32_t& lo) {
    hi = pack_bf16(f.x, f.y);
    float rx = f.x - bf16lo_f32(hi);
    float ry = f.y - bf16hi_f32(hi);
    lo = pack_bf16(rx, ry);
}

__device__ __forceinline__ void mma_bf16(float* c, const uint32_t* a, const uint32_t* b) {
    asm volatile(
        "mma.sync.aligned.m16n8k16.row.col.f32.bf16.bf16.f32 "
        "{%0,%1,%2,%3}, {%4,%5,%6,%7}, {%8,%9}, {%0,%1,%2,%3};"
        : "+f"(c[0]), "+f"(c[1]), "+f"(c[2]), "+f"(c[3])
        : "r"(a[0]), "r"(a[1]), "r"(a[2]), "r"(a[3]), "r"(b[0]), "r"(b[1]));
}

__device__ __forceinline__ void ldsm_x4(uint32_t* r, uint32_t addr) {
    asm volatile("ldmatrix.sync.aligned.m8n8.x4.shared.b16 {%0,%1,%2,%3}, [%4];"
        : "=r"(r[0]), "=r"(r[1]), "=r"(r[2]), "=r"(r[3]) : "r"(addr));
}
__device__ __forceinline__ void ldsm_x4t(uint32_t* r, uint32_t addr) {
    asm volatile("ldmatrix.sync.aligned.m8n8.x4.trans.shared.b16 {%0,%1,%2,%3}, [%4];"
        : "=r"(r[0]), "=r"(r[1]), "=r"(r[2]), "=r"(r[3]) : "r"(addr));
}

// rope one pair in fp32 then split to bf16 planes
__device__ __forceinline__ void rope_pair_store(
        float a, float b, int sg, int d, float scale,
        const float* __restrict__ cosp, const float* __restrict__ sinp,
        __nv_bfloat16* __restrict__ hi, __nv_bfloat16* __restrict__ lo, size_t obase) {
    float c1 = cosp[sg * 128 + d],      s1 = sinp[sg * 128 + d];
    float c2 = cosp[sg * 128 + d + 64], s2 = sinp[sg * 128 + d + 64];
    float o1 = (a * c1 - b * s1) * scale;
    float o2 = (b * c2 + a * s2) * scale;
    __nv_bfloat16 h1 = __float2bfloat16(o1);
    __nv_bfloat16 L1 = __float2bfloat16(o1 - __bfloat162float(h1));
    __nv_bfloat16 h2 = __float2bfloat16(o2);
    __nv_bfloat16 L2 = __float2bfloat16(o2 - __bfloat162float(h2));
    hi[obase] = h1;      lo[obase] = L1;
    hi[obase + 64] = h2; lo[obase + 64] = L2;
}

// ---------------------------------------------------------------------------
// Split kernels
// ---------------------------------------------------------------------------
__global__ void split_kernel(const float* __restrict__ in,
                             __nv_bfloat16* __restrict__ hi,
                             __nv_bfloat16* __restrict__ lo,
                             int n4) {
    int idx = blockIdx.x * blockDim.x + threadIdx.x;
    if (idx >= n4) return;
    float4 v = ((const float4*)in)[idx];
    uint32_t h01, l01, h23, l23;
    split_bf16(make_float2(v.x, v.y), h01, l01);
    split_bf16(make_float2(v.z, v.w), h23, l23);
    ((uint2*)hi)[idx] = make_uint2(h01, h23);
    ((uint2*)lo)[idx] = make_uint2(l01, l23);
}

// transpose + split: out[C,R] (bf16 hi/lo) = in[R,C] (fp32)
__global__ void transpose_split_kernel(const float* __restrict__ in,
                                       __nv_bfloat16* __restrict__ hiT,
                                       __nv_bfloat16* __restrict__ loT,
                                       int R, int C) {
    __shared__ float t[32][33];
    int c0 = blockIdx.x * 32, r0 = blockIdx.y * 32;
    int x = threadIdx.x, y = threadIdx.y;
#pragma unroll
    for (int i = y; i < 32; i += 8) t[i][x] = in[(size_t)(r0 + i) * C + c0 + x];
    __syncthreads();
#pragma unroll
    for (int i = y; i < 32; i += 8) {
        float v = t[x][i];
        __nv_bfloat16 h = __float2bfloat16(v);
        __nv_bfloat16 l = __float2bfloat16(v - __bfloat162float(h));
        size_t o = (size_t)(c0 + i) * R + r0 + x;
        hiT[o] = h;
        loT[o] = l;
    }
}

#define SROWB 56

// ---------------------------------------------------------------------------
// GEMM 128x256 wide (Q and O projections). Warp tile 64x64, 2-stage cp.async.
// If Chi != null: rope+scale+split epilogue (Q). Else: fp32 C (O).
// ---------------------------------------------------------------------------
#define WA_PL 14336
#define WB_PL 28672
#define WSTAGE_B 86016
#define GW_SMEM (2 * WSTAGE_B)   // 172032

__global__ __launch_bounds__(256, 1) void gemm_bf16p_wide(
        const __nv_bfloat16* __restrict__ Ahi, const __nv_bfloat16* __restrict__ Alo,
        const __nv_bfloat16* __restrict__ Bhi, const __nv_bfloat16* __restrict__ Blo,
        float* __restrict__ C,
        __nv_bfloat16* __restrict__ Chi, __nv_bfloat16* __restrict__ Clo,
        const float* __restrict__ cosp, const float* __restrict__ sinp, float scale,
        int M, int N, int K) {
    extern __shared__ char sm[];
    const uint32_t smem_u32 = smem_to_u32(sm);

    const int tid = threadIdx.x;
    const int wid = tid >> 5;
    const int lane = tid & 31;
    const int lr = lane & 7;
    const int lb8 = (lane >> 3) & 1;
    const int lb16 = (lane >> 4) & 1;
    const int wm = wid >> 2;
    const int wn = wid & 3;
    const int m0 = blockIdx.y * 128;
    const int n0 = blockIdx.x * 256;
    const int NS = K >> 5;

    auto load_stage = [&](int s, int buf) {
        const int k0 = s << 5;
        const uint32_t base = smem_u32 + buf * WSTAGE_B;
#pragma unroll
        for (int i = 0; i < 12; i++) {
            int c = tid + i * 256;
            if (c < 1024) {
                int pl = c >> 9;
                int idx = c & 511;
                int row = idx >> 2;
                int ch = idx & 3;
                const __nv_bfloat16* g = (pl ? Alo : Ahi) + (size_t)(m0 + row) * K + k0 + ch * 8;
                cp_async16(base + pl * WA_PL + (row * SROWB + ch * 8) * 2, g);
            } else {
                int cb = c - 1024;
                int pl = cb >> 10;
                int idx = cb & 1023;
                int row = idx >> 2;
                int ch = idx & 3;
                const __nv_bfloat16* g = (pl ? Blo : Bhi) + (size_t)(n0 + row) * K + k0 + ch * 8;
                cp_async16(base + 2 * WA_PL + pl * WB_PL + (row * SROWB + ch * 8) * 2, g);
            }
        }
    };

    float acc[4][8][4];
#pragma unroll
    for (int m = 0; m < 4; m++)
#pragma unroll
        for (int n = 0; n < 8; n++)
#pragma unroll
            for (int i = 0; i < 4; i++) acc[m][n][i] = 0.0f;

    load_stage(0, 0); cp_async_commit();
    load_stage(1, 1); cp_async_commit();

    const uint32_t a_off = ((wm * 64 + lr + lb8 * 8) * SROWB + lb16 * 8) * 2;
    const uint32_t b_off = 2 * WA_PL + ((wn * 64 + lr + lb16 * 8) * SROWB + lb8 * 8) * 2;

    for (int s = 0; s < NS; s++) {
        const int buf = s & 1;
        cp_async_wait<1>();
        __syncthreads();

        const uint32_t base = smem_u32 + buf * WSTAGE_B;

#pragma unroll
        for (int ks = 0; ks < 32; ks += 16) {
            uint32_t bhi[4][4], blo[4][4];
#pragma unroll
            for (int np = 0; np < 4; np++) {
                uint32_t addr = base + b_off + (np * 16 * SROWB + ks) * 2;
                ldsm_x4(bhi[np], addr);
                ldsm_x4(blo[np], addr + WB_PL);
            }
#pragma unroll
            for (int m = 0; m < 4; m++) {
                uint32_t ahi[4], alo[4];
                uint32_t addr = base + a_off + (m * 16 * SROWB + ks) * 2;
                ldsm_x4(ahi, addr);
                ldsm_x4(alo, addr + WA_PL);
#pragma unroll
                for (int n = 0; n < 8; n++) {
                    const uint32_t* bh = &bhi[n >> 1][(n & 1) * 2];
                    const uint32_t* bl = &blo[n >> 1][(n & 1) * 2];
                    mma_bf16(acc[m][n], ahi, bh);
                    mma_bf16(acc[m][n], ahi, bl);
                    mma_bf16(acc[m][n], alo, bh);
                }
            }
        }

        __syncthreads();
        if (s + 2 < NS) load_stage(s + 2, buf);
        cp_async_commit();
    }

    const int g = lane >> 2;
    const int tig = lane & 3;

    if (Chi) {
        // rope + scale + split epilogue via smem staging (fp32, stride 260)
        float* st = (float*)sm;
        __syncthreads();
#pragma unroll
        for (int m = 0; m < 4; m++) {
            int rl = wm * 64 + m * 16 + g;
#pragma unroll
            for (int n = 0; n < 8; n++) {
                int col = wn * 64 + n * 8 + tig * 2;
                *(float2*)&st[rl * 260 + col] = make_float2(acc[m][n][0], acc[m][n][1]);
                *(float2*)&st[(rl + 8) * 260 + col] = make_float2(acc[m][n][2], acc[m][n][3]);
            }
        }
        __syncthreads();
#pragma unroll 4
        for (int p = 0; p < 64; p++) {
            int idx = tid + p * 256;
            int row = idx >> 7;
            int rem = idx & 127;
            int hc = rem >> 6;       // head within 256-col tile
            int d = rem & 63;
            float a = st[row * 260 + hc * 128 + d];
            float b = st[row * 260 + hc * 128 + d + 64];
            int sg = m0 + row;
            size_t obase = (size_t)sg * N + n0 + hc * 128 + d;
            rope_pair_store(a, b, sg, d, scale, cosp, sinp, Chi, Clo, obase);
        }
    } else {
#pragma unroll
        for (int m = 0; m < 4; m++) {
            int r0 = m0 + wm * 64 + m * 16 + g;
            int r1 = r0 + 8;
#pragma unroll
            for (int n = 0; n < 8; n++) {
                int col = n0 + wn * 64 + n * 8 + tig * 2;
                *(float2*)(C + (size_t)r0 * N + col) = make_float2(acc[m][n][0], acc[m][n][1]);
                *(float2*)(C + (size_t)r1 * N + col) = make_float2(acc[m][n][2], acc[m][n][3]);
            }
        }
    }
}

// ---------------------------------------------------------------------------
// Fused KV projection GEMM: A[x 4096x2048] @ wkvT[1024,2048]^T.
// 128x128 tiles, NST=3 one-sync pipeline.
// Epilogue: cols 0-511 -> rope+split K planes; cols 512-1023 -> split V planes.
// ---------------------------------------------------------------------------
#define PLANE_B (128 * SROWB * 2)
#define GSTAGE_B (4 * PLANE_B)
#define GM_NST 3
#define GM_SMEM (GM_NST * GSTAGE_B)   // 172032

__global__ __launch_bounds__(256, 1) void gemm_kv(
        const __nv_bfloat16* __restrict__ Ahi, const __nv_bfloat16* __restrict__ Alo,
        const __nv_bfloat16* __restrict__ Bhi, const __nv_bfloat16* __restrict__ Blo,
        const float* __restrict__ cosp, const float* __restrict__ sinp,
        __nv_bfloat16* __restrict__ Khi, __nv_bfloat16* __restrict__ Klo,
        __nv_bfloat16* __restrict__ Vhi, __nv_bfloat16* __restrict__ Vlo) {
    extern __shared__ char sm[];
    const uint32_t smem_u32 = smem_to_u32(sm);
    const int K = D_MODEL;
    const int NS = K >> 5;

    const int tid = threadIdx.x;
    const int wid = tid >> 5;
    const int lane = tid & 31;
    const int lr = lane & 7;
    const int lb8 = (lane >> 3) & 1;
    const int lb16 = (lane >> 4) & 1;
    const int wm = wid >> 2;
    const int wn = wid & 3;
    const int m0 = blockIdx.y * 128;
    const int n0 = blockIdx.x * 128;

    const __nv_bfloat16* srcs[4] = {Ahi, Alo, Bhi, Blo};

    auto load_stage = [&](int s, int buf) {
        const int k0 = s << 5;
#pragma unroll
        for (int i = 0; i < 8; i++) {
            int c = tid + i * 256;
            int plane = c >> 9;
            int idx = c & 511;
            int row = idx >> 2;
            int ch = idx & 3;
            int grow = (plane < 2 ? m0 : n0) + row;
            const __nv_bfloat16* g = srcs[plane] + (size_t)grow * K + k0 + ch * 8;
            uint32_t dst = smem_u32 + buf * GSTAGE_B + plane * PLANE_B +
                           (row * SROWB + ch * 8) * 2;
            cp_async16(dst, g);
        }
    };

    float acc[4][4][4];
#pragma unroll
    for (int m = 0; m < 4; m++)
#pragma unroll
        for (int n = 0; n < 4; n++)
#pragma unroll
            for (int i = 0; i < 4; i++) acc[m][n][i] = 0.0f;

    load_stage(0, 0); cp_async_commit();
    load_stage(1, 1); cp_async_commit();

    const uint32_t a_off = ((wm * 64 + lr + lb8 * 8) * SROWB + lb16 * 8) * 2;
    const uint32_t b_off = 2 * PLANE_B + ((wn * 32 + lr + lb16 * 8) * SROWB + lb8 * 8) * 2;

    for (int s = 0; s < NS; s++) {
        const int buf = s % GM_NST;
        cp_async_wait<1>();
        __syncthreads();
        if (s + 2 < NS) load_stage(s + 2, (s + 2) % GM_NST);
        cp_async_commit();

        const uint32_t base = smem_u32 + buf * GSTAGE_B;

#pragma unroll
        for (int ks = 0; ks < 32; ks += 16) {
            uint32_t bhi[2][4], blo[2][4];
#pragma unroll
            for (int np = 0; np < 2; np++) {
                uint32_t addr = base + b_off + (np * 16 * SROWB + ks) * 2;
                ldsm_x4(bhi[np], addr);
                ldsm_x4(blo[np], addr + PLANE_B);
            }
#pragma unroll
            for (int m = 0; m < 4; m++) {
                uint32_t ahi[4], alo[4];
                uint32_t addr = base + a_off + (m * 16 * SROWB + ks) * 2;
                ldsm_x4(ahi, addr);
                ldsm_x4(alo, addr + PLANE_B);
#pragma unroll
                for (int n = 0; n < 4; n++) {
                    const uint32_t* bh = &bhi[n >> 1][(n & 1) * 2];
                    const uint32_t* bl = &blo[n >> 1][(n & 1) * 2];
                    mma_bf16(acc[m][n], ahi, bh);
                    mma_bf16(acc[m][n], ahi, bl);
                    mma_bf16(acc[m][n], alo, bh);
                }
            }
        }
    }

    const int g = lane >> 2;
    const int tig = lane & 3;

    if (n0 < KV_D) {
        // K region: rope + split via smem staging (fp32, stride 132)
        float* st = (float*)sm;
        __syncthreads();
#pragma unroll
        for (int m = 0; m < 4; m++) {
            int rl = wm * 64 + m * 16 + g;
#pragma unroll
            for (int n = 0; n < 4; n++) {
                int col = wn * 32 + n * 8 + tig * 2;
                *(float2*)&st[rl * 132 + col] = make_float2(acc[m][n][0], acc[m][n][1]);
                *(float2*)&st[(rl + 8) * 132 + col] = make_float2(acc[m][n][2], acc[m][n][3]);
            }
        }
        __syncthreads();
#pragma unroll 4
        for (int p = 0; p < 32; p++) {
            int idx = tid + p * 256;
            int row = idx >> 6;
            int d = idx & 63;
            float a = st[row * 132 + d];
            float b = st[row * 132 + d + 64];
            int sg = m0 + row;
            size_t obase = (size_t)sg * KV_D + n0 + d;
            rope_pair_store(a, b, sg, d, 1.0f, cosp, sinp, Khi, Klo, obase);
        }
    } else {
        // V region: plain split
#pragma unroll
        for (int m = 0; m < 4; m++) {
            int r0 = m0 + wm * 64 + m * 16 + g;
            int r1 = r0 + 8;
#pragma unroll
            for (int n = 0; n < 4; n++) {
                int col = n0 - KV_D + wn * 32 + n * 8 + tig * 2;
                uint32_t h0, lo0, h1, lo1;
                split_bf16(make_float2(acc[m][n][0], acc[m][n][1]), h0, lo0);
                split_bf16(make_float2(acc[m][n][2], acc[m][n][3]), h1, lo1);
                *(uint32_t*)&Vhi[(size_t)r0 * KV_D + col] = h0;
                *(uint32_t*)&Vlo[(size_t)r0 * KV_D + col] = lo0;
                *(uint32_t*)&Vhi[(size_t)r1 * KV_D + col] = h1;
                *(uint32_t*)&Vlo[(size_t)r1 * KV_D + col] = lo1;
            }
        }
    }
}

// ---------------------------------------------------------------------------
// Flash attention: work-sorted 1D grid (heaviest q-tiles first, all heads
// of a tile adjacent for KV L2 reuse).
// ---------------------------------------------------------------------------
#define QROW 136
#define FOFF_QLO 34816
#define FSTAGE0 69632
#define FSTAGE_B 69632
#define FKLO 17408
#define FVHI 34816
#define FVLO 52224
#define FB_SMEM 208896

__global__ __launch_bounds__(256, 1) void flash_attn_mma2(
        const __nv_bfloat16* __restrict__ Qhi, const __nv_bfloat16* __restrict__ Qlo,
        const __nv_bfloat16* __restrict__ Khi, const __nv_bfloat16* __restrict__ Klo,
        const __nv_bfloat16* __restrict__ Vhi, const __nv_bfloat16* __restrict__ Vlo,
        __nv_bfloat16* __restrict__ Ohi, __nv_bfloat16* __restrict__ Olo) {
    extern __shared__ char sm[];
    const uint32_t smem_u32 = smem_to_u32(sm);

    const int b = blockIdx.x;
    const int qt = (int)(gridDim.x >> 4) - 1 - (b >> 4);
    const int h = b & 15;
    const int kvg = h >> 2;
    const int tid = threadIdx.x;
    const int w = tid >> 5;
    const int lane = tid & 31;
    const int lr = lane & 7;
    const int lb8 = (lane >> 3) & 1;
    const int lb16 = (lane >> 4) & 1;
    const int lg = lane >> 2;
    const int tig = lane & 3;
    const int q0 = qt * 128;
    const int qb = w * 16;

    const __nv_bfloat16* kvsrc[4] = {Khi, Klo, Vhi, Vlo};

    auto load_kv = [&](int jt, int buf) {
        const size_t rowbase = (size_t)(jt * 64) * KV_D + kvg * HD;
#pragma unroll
        for (int i = 0; i < 16; i++) {
            int c = tid + i * 256;
            int plane = c >> 10;
            int idx = c & 1023;
            int row = idx >> 4;
            int ch = idx & 15;
            const __nv_bfloat16* src = kvsrc[plane] + rowbase + (size_t)row * KV_D + ch * 8;
            uint32_t dst = smem_u32 + FSTAGE0 + buf * FSTAGE_B + plane * 17408 +
                           (row * QROW + ch * 8) * 2;
            cp_async16(dst, src);
        }
    };

#pragma unroll
    for (int i = 0; i < 16; i++) {
        int c = tid + i * 256;
        int plane = c >> 11;
        int idx = c & 2047;
        int row = idx >> 4;
        int ch = idx & 15;
        const __nv_bfloat16* src = (plane ? Qlo : Qhi) +
            (size_t)(q0 + row) * D_MODEL + h * HD + ch * 8;
        uint32_t dst = smem_u32 + plane * FOFF_QLO + (row * QROW + ch * 8) * 2;
        cp_async16(dst, src);
    }
    load_kv(0, 0);
    cp_async_commit();
    load_kv(1, 1);
    cp_async_commit();

    const uint32_t qa_hi = smem_u32 + ((qb + lb8 * 8 + lr) * QROW + lb16 * 8) * 2;
    const uint32_t qa_lo = qa_hi + FOFF_QLO;
    const uint32_t k_off = ((lb16 * 8 + lr) * QROW + lb8 * 8) * 2;
    const uint32_t v_off = ((lb8 * 8 + lr) * QROW + lb16 * 8) * 2;

    float m0 = -1e30f, m1 = -1e30f, l0 = 0.0f, l1 = 0.0f;
    float oacc[16][4];
#pragma unroll
    for (int nt = 0; nt < 16; nt++)
#pragma unroll
        for (int j = 0; j < 4; j++) oacc[nt][j] = 0.0f;

    const int njt = 2 * qt + 2;
    for (int jt = 0; jt < njt; jt++) {
        cp_async_wait<1>();
        __syncthreads();

        const bool active = (jt * 64 <= q0 + qb + 15);
        if (active) {
            const uint32_t kvbase = smem_u32 + FSTAGE0 + (jt & 1) * FSTAGE_B;

            float sacc[8][4];
#pragma unroll
            for (int nt = 0; nt < 8; nt++)
#pragma unroll
                for (int j = 0; j < 4; j++) sacc[nt][j] = 0.0f;

#pragma unroll
            for (int kc = 0; kc < 8; kc++) {
                uint32_t qhi[4], qlo[4];
                ldsm_x4(qhi, qa_hi + kc * 32);
                ldsm_x4(qlo, qa_lo + kc * 32);
#pragma unroll
                for (int ntp = 0; ntp < 4; ntp++) {
                    uint32_t khi[4], klo[4];
                    uint32_t ka = kvbase + k_off + ntp * (16 * QROW * 2) + kc * 32;
                    ldsm_x4(khi, ka);
                    ldsm_x4(klo, ka + FKLO);
                    mma_bf16(sacc[2 * ntp], qhi, khi);
                    mma_bf16(sacc[2 * ntp], qhi, klo);
                    mma_bf16(sacc[2 * ntp], qlo, khi);
                    mma_bf16(sacc[2 * ntp + 1], qhi, khi + 2);
                    mma_bf16(sacc[2 * ntp + 1], qhi, klo + 2);
                    mma_bf16(sacc[2 * ntp + 1], qlo, khi + 2);
                }
            }

            if (jt * 64 + 63 > q0 + qb) {
#pragma unroll
                for (int nt = 0; nt < 8; nt++)
#pragma unroll
                    for (int j = 0; j < 4; j++) {
                        int gj = jt * 64 + nt * 8 + tig * 2 + (j & 1);
                        int gi = q0 + qb + lg + ((j >> 1) << 3);
                        if (gj > gi) sacc[nt][j] = -1e30f;
                    }
            }

            float cur0 = -1e30f, cur1 = -1e30f;
#pragma unroll
            for (int nt = 0; nt < 8; nt++) {
                cur0 = fmaxf(cur0, fmaxf(sacc[nt][0], sacc[nt][1]));
                cur1 = fmaxf(cur1, fmaxf(sacc[nt][2], sacc[nt][3]));
            }
            cur0 = fmaxf(cur0, __shfl_xor_sync(0xffffffffu, cur0, 1));
            cur0 = fmaxf(cur0, __shfl_xor_sync(0xffffffffu, cur0, 2));
            cur1 = fmaxf(cur1, __shfl_xor_sync(0xffffffffu, cur1, 1));
            cur1 = fmaxf(cur1, __shfl_xor_sync(0xffffffffu, cur1, 2));

            float mn0 = fmaxf(m0, cur0), mn1 = fmaxf(m1, cur1);
            float alpha0 = __expf(m0 - mn0), alpha1 = __expf(m1 - mn1);
            m0 = mn0; m1 = mn1;

            float rs0 = 0.0f, rs1 = 0.0f;
#pragma unroll
            for (int nt = 0; nt < 8; nt++) {
                sacc[nt][0] = __expf(sacc[nt][0] - mn0);
                sacc[nt][1] = __expf(sacc[nt][1] - mn0);
                sacc[nt][2] = __expf(sacc[nt][2] - mn1);
                sacc[nt][3] = __expf(sacc[nt][3] - mn1);
                rs0 += sacc[nt][0] + sacc[nt][1];
                rs1 += sacc[nt][2] + sacc[nt][3];
            }
            rs0 += __shfl_xor_sync(0xffffffffu, rs0, 1);
            rs0 += __shfl_xor_sync(0xffffffffu, rs0, 2);
            rs1 += __shfl_xor_sync(0xffffffffu, rs1, 1);
            rs1 += __shfl_xor_sync(0xffffffffu, rs1, 2);
            l0 = l0 * alpha0 + rs0;
            l1 = l1 * alpha1 + rs1;

#pragma unroll
            for (int nt = 0; nt < 16; nt++) {
                oacc[nt][0] *= alpha0;
                oacc[nt][1] *= alpha0;
                oacc[nt][2] *= alpha1;
                oacc[nt][3] *= alpha1;
            }

#pragma unroll
            for (int kc = 0; kc < 4; kc++) {
                uint32_t ahi[4], alo[4];
                split_bf16(make_float2(sacc[2 * kc][0], sacc[2 * kc][1]), ahi[0], alo[0]);
                split_bf16(make_float2(sacc[2 * kc][2], sacc[2 * kc][3]), ahi[1], alo[1]);
                split_bf16(make_float2(sacc[2 * kc + 1][0], sacc[2 * kc + 1][1]), ahi[2], alo[2]);
                split_bf16(make_float2(sacc[2 * kc + 1][2], sacc[2 * kc + 1][3]), ahi[3], alo[3]);
#pragma unroll
                for (int ntp = 0; ntp < 8; ntp++) {
                    uint32_t vh[4], vl[4];
                    uint32_t va = kvbase + FVHI + v_off + kc * (16 * QROW * 2) + ntp * 32;
                    ldsm_x4t(vh, va);
                    ldsm_x4t(vl, va + (FVLO - FVHI));
                    mma_bf16(oacc[2 * ntp], ahi, vh);
                    mma_bf16(oacc[2 * ntp], alo, vh);
                    mma_bf16(oacc[2 * ntp], ahi, vl);
                    mma_bf16(oacc[2 * ntp + 1], ahi, vh + 2);
                    mma_bf16(oacc[2 * ntp + 1], alo, vh + 2);
                    mma_bf16(oacc[2 * ntp + 1], ahi, vl + 2);
                }
            }
        }

        __syncthreads();
        if (jt + 2 < njt) load_kv(jt + 2, jt & 1);
        cp_async_commit();
    }

    float inv0 = 1.0f / l0;
    float inv1 = 1.0f / l1;
    int row0 = q0 + qb + lg;
    int row1 = row0 + 8;
#pragma unroll
    for (int nt = 0; nt < 16; nt++) {
        int col = h * HD + nt * 8 + tig * 2;
        uint32_t h0, lo0, h1, lo1;
        split_bf16(make_float2(oacc[nt][0] * inv0, oacc[nt][1] * inv0), h0, lo0);
        split_bf16(make_float2(oacc[nt][2] * inv1, oacc[nt][3] * inv1), h1, lo1);
        *(uint32_t*)&Ohi[(size_t)row0 * D_MODEL + col] = h0;
        *(uint32_t*)&Olo[(size_t)row0 * D_MODEL + col] = lo0;
        *(uint32_t*)&Ohi[(size_t)row1 * D_MODEL + col] = h1;
        *(uint32_t*)&Olo[(size_t)row1 * D_MODEL + col] = lo1;
    }
}

// ---------------------------------------------------------------------------
extern "C" void kernel_launch(void* const* d_in, const int* in_sizes, int n_in,
                              void* d_out, int out_size) {
    const float* x    = (const float*)d_in[0];
    const float* wq   = (const float*)d_in[2];
    const float* wk   = (const float*)d_in[3];
    const float* wv   = (const float*)d_in[4];
    const float* wo   = (const float*)d_in[5];
    const float* cosp = (const float*)d_in[6];
    const float* sinp = (const float*)d_in[7];
    float* out = (float*)d_out;

    __nv_bfloat16 *xhi, *xlo, *qhi, *qlo, *khi, *klo, *vhi, *vlo, *ctxhi, *ctxlo;
    __nv_bfloat16 *wqThi, *wqTlo, *wkvThi, *wkvTlo, *woThi, *woTlo;
    cudaGetSymbolAddress((void**)&xhi, g_xhi);
    cudaGetSymbolAddress((void**)&xlo, g_xlo);
    cudaGetSymbolAddress((void**)&qhi, g_qhi);
    cudaGetSymbolAddress((void**)&qlo, g_qlo);
    cudaGetSymbolAddress((void**)&khi, g_khi);
    cudaGetSymbolAddress((void**)&klo, g_klo);
    cudaGetSymbolAddress((void**)&vhi, g_vhi);
    cudaGetSymbolAddress((void**)&vlo, g_vlo);
    cudaGetSymbolAddress((void**)&ctxhi, g_ctxhi);
    cudaGetSymbolAddress((void**)&ctxlo, g_ctxlo);
    cudaGetSymbolAddress((void**)&wqThi, g_wqThi);
    cudaGetSymbolAddress((void**)&wqTlo, g_wqTlo);
    cudaGetSymbolAddress((void**)&wkvThi, g_wkvThi);
    cudaGetSymbolAddress((void**)&wkvTlo, g_wkvTlo);
    cudaGetSymbolAddress((void**)&woThi, g_woThi);
    cudaGetSymbolAddress((void**)&woTlo, g_woTlo);

    cudaFuncSetAttribute(gemm_bf16p_wide, cudaFuncAttributeMaxDynamicSharedMemorySize, GW_SMEM);
    cudaFuncSetAttribute(gemm_kv, cudaFuncAttributeMaxDynamicSharedMemorySize, GM_SMEM);
    cudaFuncSetAttribute(flash_attn_mma2, cudaFuncAttributeMaxDynamicSharedMemorySize, FB_SMEM);

    // Pre-split x and weights
    {
        int n4 = S_LEN * D_MODEL / 4;
        split_kernel<<<(n4 + 255) / 256, 256>>>(x, xhi, xlo, n4);
    }
    transpose_split_kernel<<<dim3(D_MODEL / 32, D_MODEL / 32), dim3(32, 8)>>>(
        wq, wqThi, wqTlo, D_MODEL, D_MODEL);
    transpose_split_kernel<<<dim3(KV_D / 32, D_MODEL / 32), dim3(32, 8)>>>(
        wk, wkvThi, wkvTlo, D_MODEL, KV_D);
    transpose_split_kernel<<<dim3(KV_D / 32, D_MODEL / 32), dim3(32, 8)>>>(
        wv, wkvThi + (size_t)KV_D * D_MODEL, wkvTlo + (size_t)KV_D * D_MODEL, D_MODEL, KV_D);
    transpose_split_kernel<<<dim3(D_MODEL / 32, D_MODEL / 32), dim3(32, 8)>>>(
        wo, woThi, woTlo, D_MODEL, D_MODEL);

    // Q projection with fused rope+scale+split epilogue
    gemm_bf16p_wide<<<dim3(D_MODEL / 256, S_LEN / 128), 256, GW_SMEM>>>(
        xhi, xlo, wqThi, wqTlo, nullptr, qhi, qlo, cosp, sinp, SOFTMAX_SCALE,
        S_LEN, D_MODEL, D_MODEL);

    // Fused K+V projection (K gets rope+split, V gets split)
    gemm_kv<<<dim3(2 * KV_D / 128, S_LEN / 128), 256, GM_SMEM>>>(
        xhi, xlo, wkvThi, wkvTlo, cosp, sinp, khi, klo, vhi, vlo);

    // Flash attention (writes ctx hi/lo planes)
    flash_attn_mma2<<<dim3((S_LEN / 128) * NH, 1), 256, FB_SMEM>>>(
        qhi, qlo, khi, klo, vhi, vlo, ctxhi, ctxlo);

    // Output projection (fp32 out)
    gemm_bf16p_wide<<<dim3(D_MODEL / 256, S_LEN / 128), 256, GW_SMEM>>>(
        ctxhi, ctxlo, woThi, woTlo, out, nullptr, nullptr, nullptr, nullptr, 1.0f,
        S_LEN, D_MODEL, D_MODEL);
}